// round 1
// baseline (speedup 1.0000x reference)
#include <cuda_runtime.h>

#define C_    256
#define B_    4
#define N_    4096
#define EPSF  1e-3f
#define LOG2E 1.4426950408889634f
#define CHUNKS 32

// ---- scratch (device globals, no allocations) ----
__device__ float g_partial[B_ * CHUNKS * C_];
__device__ float g_gap[B_ * C_];
__device__ float g_wf[B_ * C_ * 3];   // per-batch fused qkv weights (a_c * w_qkv[c][f])
__device__ float g_cf[B_ * 3];        // per-batch constant term  (sum_c d_c * w_qkv[c][f])
__device__ float g_qs[B_ * N_];
__device__ float g_ks[B_ * N_];
__device__ float g_vs[B_ * N_];
__device__ float g_kmax[B_];
__device__ float g_kmin[B_];

__device__ __forceinline__ float ex2f(float x) {
    float r;
    asm("ex2.approx.ftz.f32 %0, %1;" : "=f"(r) : "f"(x));
    return r;
}

// ---------------------------------------------------------------------------
// K1a: partial sums for global average pool over (H,W). grid (CHUNKS, B), 256 thr
// ---------------------------------------------------------------------------
__global__ void k_gap_partial(const float* __restrict__ x) {
    int b = blockIdx.y, ch = blockIdx.x, t = threadIdx.x;
    const float* p = x + ((size_t)(b * N_) + (size_t)ch * (N_ / CHUNKS)) * C_ + t;
    float s = 0.f;
#pragma unroll 8
    for (int i = 0; i < N_ / CHUNKS; i++) s += p[(size_t)i * C_];
    g_partial[(b * CHUNKS + ch) * C_ + t] = s;
}

// K1b: finish GAP. grid B, 256 thr
__global__ void k_gap_final() {
    int b = blockIdx.x, t = threadIdx.x;
    float s = 0.f;
#pragma unroll
    for (int ch = 0; ch < CHUNKS; ch++) s += g_partial[(b * CHUNKS + ch) * C_ + t];
    g_gap[b * C_ + t] = s * (1.0f / N_);
}

// ---------------------------------------------------------------------------
// K2: channel attention + percentile mask + fused weight precompute.
// grid B, 256 thr (thread t == channel t)
// ---------------------------------------------------------------------------
__global__ void k_channel(const float* __restrict__ ca_g, const float* __restrict__ ca_b,
                          const float* __restrict__ ca_m, const float* __restrict__ ca_v,
                          const float* __restrict__ wq,   const float* __restrict__ wk,
                          const float* __restrict__ wv,   const float* __restrict__ wp,
                          const float* __restrict__ bn_g, const float* __restrict__ bn_b,
                          const float* __restrict__ bn_m, const float* __restrict__ bn_v,
                          const float* __restrict__ wqkv) {
    __shared__ float sh_gn[C_], sh_k[C_], sh_v[C_], sh_att[C_], sh_cm[C_], sh_d[C_];
    __shared__ float sh_thr[2];
    int b = blockIdx.x, t = threadIdx.x;

    // BN on gap
    float gap = g_gap[b * C_ + t];
    float gn  = (gap - ca_m[t]) * rsqrtf(ca_v[t] + EPSF) * ca_g[t] + ca_b[t];
    sh_gn[t] = gn;
    __syncthreads();

    // q,k,v = gn @ W (column t)
    float q = 0.f, kk = 0.f, vv = 0.f;
#pragma unroll 4
    for (int c = 0; c < C_; c++) {
        float g = sh_gn[c];
        q  = fmaf(g, wq[c * C_ + t], q);
        kk = fmaf(g, wk[c * C_ + t], kk);
        vv = fmaf(g, wv[c * C_ + t], vv);
    }
    sh_k[t] = kk; sh_v[t] = vv;
    __syncthreads();

    // softmax over j of q_t * k_j, weighted by v_j
    float kmx = -1e30f, kmn = 1e30f;
#pragma unroll 4
    for (int c = 0; c < C_; c++) {
        float kc = sh_k[c];
        kmx = fmaxf(kmx, kc); kmn = fminf(kmn, kc);
    }
    float m  = (q >= 0.f) ? q * kmx : q * kmn;
    float c1 = q * LOG2E, mb = m * LOG2E;
    float num = 0.f, den = 0.f;
#pragma unroll 4
    for (int j = 0; j < C_; j++) {
        float e = ex2f(fmaf(c1, sh_k[j], -mb));
        den += e;
        num = fmaf(e, sh_v[j], num);
    }
    sh_att[t] = num / den;
    __syncthreads();

    // cmask = sigmoid(att @ wp)
    float s = 0.f;
#pragma unroll 4
    for (int c = 0; c < C_; c++) s = fmaf(sh_att[c], wp[c * C_ + t], s);
    float cm = 1.0f / (1.0f + ex2f(-s * LOG2E));
    sh_cm[t] = cm;
    __syncthreads();

    // 10th percentile (linear): pos = 0.1*(256-1) = 25.5 -> 0.5*(s[25]+s[26])
    int rank = 0;
#pragma unroll 4
    for (int j = 0; j < C_; j++) {
        float cj = sh_cm[j];
        rank += (cj < cm) || (cj == cm && j < t);
    }
    if (rank == 25) sh_thr[0] = cm;
    if (rank == 26) sh_thr[1] = cm;
    __syncthreads();
    float thr = 0.5f * (sh_thr[0] + sh_thr[1]);
    float pm  = (cm > thr) ? cm : 0.f;

    // co = ((x*(1+cm) - bn_m)*rs*g + bn_b) * pm  ==  a*x + d
    float rs = rsqrtf(bn_v[t] + EPSF) * bn_g[t];
    float a  = (1.f + cm) * rs * pm;
    float d  = (bn_b[t] - bn_m[t] * rs) * pm;

#pragma unroll
    for (int f = 0; f < 3; f++) g_wf[(b * C_ + t) * 3 + f] = a * wqkv[t * 3 + f];
    sh_d[t] = d;
    __syncthreads();
    if (t < 3) {
        float cf = 0.f;
        for (int c = 0; c < C_; c++) cf = fmaf(sh_d[c], wqkv[c * 3 + t], cf);
        g_cf[b * 3 + t] = cf;
    }
}

// ---------------------------------------------------------------------------
// K3: qkv projection. grid (16, B), 256 thr; thread t owns pixel s.
// ---------------------------------------------------------------------------
__global__ void k_qkv(const float* __restrict__ x) {
    __shared__ float swf[C_ * 3];
    __shared__ float scf[3];
    int b = blockIdx.y, t = threadIdx.x;
    for (int i = t; i < C_ * 3; i += 256) swf[i] = g_wf[b * C_ * 3 + i];
    if (t < 3) scf[t] = g_cf[b * 3 + t];
    __syncthreads();

    int s = blockIdx.x * 256 + t;
    const float4* xp = (const float4*)(x + ((size_t)(b * N_ + s)) * C_);
    float q = 0.f, k = 0.f, v = 0.f;
#pragma unroll 8
    for (int u = 0; u < C_ / 4; u++) {
        float4 a = xp[u];
        const float* w = &swf[(4 * u) * 3];
        q = fmaf(a.x, w[0], q);  k = fmaf(a.x, w[1], k);  v = fmaf(a.x, w[2], v);
        q = fmaf(a.y, w[3], q);  k = fmaf(a.y, w[4], k);  v = fmaf(a.y, w[5], v);
        q = fmaf(a.z, w[6], q);  k = fmaf(a.z, w[7], k);  v = fmaf(a.z, w[8], v);
        q = fmaf(a.w, w[9], q);  k = fmaf(a.w, w[10], k); v = fmaf(a.w, w[11], v);
    }
    g_qs[b * N_ + s] = q + scf[0];
    g_ks[b * N_ + s] = k + scf[1];
    g_vs[b * N_ + s] = v + scf[2];
}

// ---------------------------------------------------------------------------
// K4: per-batch min/max of k. grid B, 256 thr
// ---------------------------------------------------------------------------
__global__ void k_minmax() {
    __shared__ float smx[256], smn[256];
    int b = blockIdx.x, t = threadIdx.x;
    float mx = -1e30f, mn = 1e30f;
    for (int i = t; i < N_; i += 256) {
        float k = g_ks[b * N_ + i];
        mx = fmaxf(mx, k); mn = fminf(mn, k);
    }
    smx[t] = mx; smn[t] = mn;
    __syncthreads();
    for (int o = 128; o > 0; o >>= 1) {
        if (t < o) { smx[t] = fmaxf(smx[t], smx[t + o]); smn[t] = fminf(smn[t], smn[t + o]); }
        __syncthreads();
    }
    if (t == 0) { g_kmax[b] = smx[0]; g_kmin[b] = smn[0]; }
}

// ---------------------------------------------------------------------------
// K5: spatial softmax attention. grid (32, B), 256 thr (8 warps).
// Each block: k/v resident in SMEM, 128 query rows, one warp per row.
// ---------------------------------------------------------------------------
__global__ void k_attn(float* __restrict__ out) {
    __shared__ float sk[N_];
    __shared__ float sv[N_];
    int b = blockIdx.y, t = threadIdx.x, lane = t & 31, wid = t >> 5;

    const float4* kp = (const float4*)(g_ks + b * N_);
    const float4* vp = (const float4*)(g_vs + b * N_);
    float4* skp = (float4*)sk;
    float4* svp = (float4*)sv;
    for (int i = t; i < N_ / 4; i += 256) { skp[i] = kp[i]; svp[i] = vp[i]; }
    __syncthreads();

    float kmx = g_kmax[b], kmn = g_kmin[b];
    int i_base = blockIdx.x * 128;

    for (int it = 0; it < 16; it++) {
        int i   = i_base + it * 8 + wid;
        float qi = g_qs[b * N_ + i];
        float m  = (qi >= 0.f) ? qi * kmx : qi * kmn;
        float c1 = qi * LOG2E, mb = m * LOG2E;

        float n0 = 0.f, n1 = 0.f, d0 = 0.f, d1 = 0.f;
#pragma unroll 4
        for (int j = lane; j < N_; j += 64) {
            float e0 = ex2f(fmaf(c1, sk[j], -mb));
            d0 += e0;
            n0 = fmaf(e0, sv[j], n0);
            float e1 = ex2f(fmaf(c1, sk[j + 32], -mb));
            d1 += e1;
            n1 = fmaf(e1, sv[j + 32], n1);
        }
        float num = n0 + n1, den = d0 + d1;
#pragma unroll
        for (int o = 16; o > 0; o >>= 1) {
            num += __shfl_xor_sync(0xffffffffu, num, o);
            den += __shfl_xor_sync(0xffffffffu, den, o);
        }
        if (lane == 0) out[b * N_ + i] = sv[i] + num / den;
    }
}

// ---------------------------------------------------------------------------
extern "C" void kernel_launch(void* const* d_in, const int* in_sizes, int n_in,
                              void* d_out, int out_size) {
    const float* x       = (const float*)d_in[0];
    const float* ca_g    = (const float*)d_in[1];
    const float* ca_b    = (const float*)d_in[2];
    const float* ca_m    = (const float*)d_in[3];
    const float* ca_v    = (const float*)d_in[4];
    const float* wq      = (const float*)d_in[5];
    const float* wk      = (const float*)d_in[6];
    const float* wv      = (const float*)d_in[7];
    const float* wp      = (const float*)d_in[8];
    const float* bn_g    = (const float*)d_in[9];
    const float* bn_b    = (const float*)d_in[10];
    const float* bn_m    = (const float*)d_in[11];
    const float* bn_v    = (const float*)d_in[12];
    const float* wqkv    = (const float*)d_in[13];
    float* out = (float*)d_out;

    k_gap_partial<<<dim3(CHUNKS, B_), C_>>>(x);
    k_gap_final<<<B_, C_>>>();
    k_channel<<<B_, C_>>>(ca_g, ca_b, ca_m, ca_v, wq, wk, wv, wp,
                          bn_g, bn_b, bn_m, bn_v, wqkv);
    k_qkv<<<dim3(16, B_), 256>>>(x);
    k_minmax<<<B_, 256>>>();
    k_attn<<<dim3(32, B_), 256>>>(out);
}

// round 2
// speedup vs baseline: 1.2827x; 1.2827x over previous
#include <cuda_runtime.h>

#define C_    256
#define B_    4
#define N_    4096
#define EPSF  1e-3f
#define LOG2E 1.4426950408889634f
#define CHUNKS 64
#define RPB   56   // rows per attention block; 74 blocks/batch * 56 >= 4096

// ---- scratch (device globals, no allocations) ----
__device__ float g_partial[B_ * CHUNKS * C_];
__device__ float g_wf[B_ * C_ * 3];   // per-batch fused qkv weights (a_c * w_qkv[c][f])
__device__ float g_cf[B_ * 3];        // per-batch constant term
__device__ float g_qs[B_ * N_];
__device__ float g_ks[B_ * N_];
__device__ float g_vs[B_ * N_];
__device__ unsigned g_kmax_u[B_];
__device__ unsigned g_kmin_u[B_];

__device__ __forceinline__ float ex2f(float x) {
    float r;
    asm("ex2.approx.ftz.f32 %0, %1;" : "=f"(r) : "f"(x));
    return r;
}
// order-preserving float<->uint for atomic min/max
__device__ __forceinline__ unsigned encf(float f) {
    unsigned u = __float_as_uint(f);
    return (u & 0x80000000u) ? ~u : (u | 0x80000000u);
}
__device__ __forceinline__ float decf(unsigned u) {
    return __uint_as_float((u & 0x80000000u) ? (u ^ 0x80000000u) : ~u);
}

// ---------------------------------------------------------------------------
// K1: partial sums for global average pool. grid (CHUNKS, B), 256 thr.
// Also initializes the min/max atomics (consumed later by k_qkv).
// ---------------------------------------------------------------------------
__global__ void k_gap_partial(const float* __restrict__ x) {
    int b = blockIdx.y, ch = blockIdx.x, t = threadIdx.x;
    if (blockIdx.x == 0 && blockIdx.y == 0 && t < B_) {
        g_kmax_u[t] = 0u;
        g_kmin_u[t] = 0xffffffffu;
    }
    const float* p = x + ((size_t)(b * N_) + (size_t)ch * (N_ / CHUNKS)) * C_ + t;
    float s = 0.f;
#pragma unroll 8
    for (int i = 0; i < N_ / CHUNKS; i++) s += p[(size_t)i * C_];
    g_partial[(b * CHUNKS + ch) * C_ + t] = s;
}

// ---------------------------------------------------------------------------
// K2: gap-final + channel attention + percentile mask + fused weights.
// grid B, 256 thr (thread t == channel t)
// ---------------------------------------------------------------------------
__global__ void k_channel(const float* __restrict__ ca_g, const float* __restrict__ ca_b,
                          const float* __restrict__ ca_m, const float* __restrict__ ca_v,
                          const float* __restrict__ wq,   const float* __restrict__ wk,
                          const float* __restrict__ wv,   const float* __restrict__ wp,
                          const float* __restrict__ bn_g, const float* __restrict__ bn_b,
                          const float* __restrict__ bn_m, const float* __restrict__ bn_v,
                          const float* __restrict__ wqkv) {
    __shared__ float sh_gn[C_], sh_k[C_], sh_v[C_], sh_att[C_], sh_cm[C_], sh_d[C_];
    __shared__ float sh_thr[2];
    int b = blockIdx.x, t = threadIdx.x;

    // finish GAP
    float s0 = 0.f;
#pragma unroll 8
    for (int ch = 0; ch < CHUNKS; ch++) s0 += g_partial[(b * CHUNKS + ch) * C_ + t];
    float gap = s0 * (1.0f / N_);

    // BN on gap
    float gn = (gap - ca_m[t]) * rsqrtf(ca_v[t] + EPSF) * ca_g[t] + ca_b[t];
    sh_gn[t] = gn;
    __syncthreads();

    // q,k,v = gn @ W (column t)
    float q = 0.f, kk = 0.f, vv = 0.f;
#pragma unroll 4
    for (int c = 0; c < C_; c++) {
        float g = sh_gn[c];
        q  = fmaf(g, wq[c * C_ + t], q);
        kk = fmaf(g, wk[c * C_ + t], kk);
        vv = fmaf(g, wv[c * C_ + t], vv);
    }
    sh_k[t] = kk; sh_v[t] = vv;
    __syncthreads();

    // softmax over j of q_t * k_j, weighted by v_j
    float kmx = -1e30f, kmn = 1e30f;
#pragma unroll 4
    for (int c = 0; c < C_; c++) {
        float kc = sh_k[c];
        kmx = fmaxf(kmx, kc); kmn = fminf(kmn, kc);
    }
    float m  = (q >= 0.f) ? q * kmx : q * kmn;
    float c1 = q * LOG2E, mb = m * LOG2E;
    float num = 0.f, den = 0.f;
#pragma unroll 4
    for (int j = 0; j < C_; j++) {
        float e = ex2f(fmaf(c1, sh_k[j], -mb));
        den += e;
        num = fmaf(e, sh_v[j], num);
    }
    sh_att[t] = num / den;
    __syncthreads();

    // cmask = sigmoid(att @ wp)
    float s = 0.f;
#pragma unroll 4
    for (int c = 0; c < C_; c++) s = fmaf(sh_att[c], wp[c * C_ + t], s);
    float cm = 1.0f / (1.0f + ex2f(-s * LOG2E));
    sh_cm[t] = cm;
    __syncthreads();

    // 10th percentile (linear): pos = 0.1*(256-1) = 25.5 -> 0.5*(s[25]+s[26])
    int rank = 0;
#pragma unroll 4
    for (int j = 0; j < C_; j++) {
        float cj = sh_cm[j];
        rank += (cj < cm) || (cj == cm && j < t);
    }
    if (rank == 25) sh_thr[0] = cm;
    if (rank == 26) sh_thr[1] = cm;
    __syncthreads();
    float thr = 0.5f * (sh_thr[0] + sh_thr[1]);
    float pm  = (cm > thr) ? cm : 0.f;

    // co = ((x*(1+cm) - bn_m)*rs*g + bn_b) * pm  ==  a*x + d
    float rs = rsqrtf(bn_v[t] + EPSF) * bn_g[t];
    float a  = (1.f + cm) * rs * pm;
    float d  = (bn_b[t] - bn_m[t] * rs) * pm;

#pragma unroll
    for (int f = 0; f < 3; f++) g_wf[(b * C_ + t) * 3 + f] = a * wqkv[t * 3 + f];
    sh_d[t] = d;
    __syncthreads();
    if (t < 3) {
        float cf = 0.f;
        for (int c = 0; c < C_; c++) cf = fmaf(sh_d[c], wqkv[c * 3 + t], cf);
        g_cf[b * 3 + t] = cf;
    }
}

// ---------------------------------------------------------------------------
// K3: qkv projection, warp-per-pixel. grid (32, B), 256 thr (8 warps).
// Lane l owns channels {4l..4l+3, 128+4l..128+4l+3}: weights live in regs,
// x reads are 2 fully-coalesced LDG.128 per pixel. Butterfly reduce.
// Also accumulates per-batch k min/max via atomics.
// ---------------------------------------------------------------------------
__global__ void k_qkv(const float* __restrict__ x) {
    int b = blockIdx.y, t = threadIdx.x, lane = t & 31, wid = t >> 5;

    const float* wf = g_wf + b * C_ * 3;
    float wq_[8], wk_[8], wv_[8];
#pragma unroll
    for (int i = 0; i < 4; i++) {
        int c0 = 4 * lane + i, c1 = 128 + 4 * lane + i;
        wq_[i]     = wf[c0 * 3 + 0]; wk_[i]     = wf[c0 * 3 + 1]; wv_[i]     = wf[c0 * 3 + 2];
        wq_[4 + i] = wf[c1 * 3 + 0]; wk_[4 + i] = wf[c1 * 3 + 1]; wv_[4 + i] = wf[c1 * 3 + 2];
    }
    float cf0 = g_cf[b * 3 + 0], cf1 = g_cf[b * 3 + 1], cf2 = g_cf[b * 3 + 2];

    const float4* x4 = (const float4*)(x + (size_t)b * N_ * C_);
    int wg = blockIdx.x * 8 + wid;            // warp index within batch: 0..255
    float lmax = -1e30f, lmin = 1e30f;

#pragma unroll 2
    for (int it = 0; it < 16; it++) {
        int p = wg * 16 + it;
        float4 a0 = x4[(size_t)p * 64 + lane];
        float4 a1 = x4[(size_t)p * 64 + 32 + lane];
        float q, k, v;
        q = a0.x * wq_[0]; k = a0.x * wk_[0]; v = a0.x * wv_[0];
        q = fmaf(a0.y, wq_[1], q); k = fmaf(a0.y, wk_[1], k); v = fmaf(a0.y, wv_[1], v);
        q = fmaf(a0.z, wq_[2], q); k = fmaf(a0.z, wk_[2], k); v = fmaf(a0.z, wv_[2], v);
        q = fmaf(a0.w, wq_[3], q); k = fmaf(a0.w, wk_[3], k); v = fmaf(a0.w, wv_[3], v);
        q = fmaf(a1.x, wq_[4], q); k = fmaf(a1.x, wk_[4], k); v = fmaf(a1.x, wv_[4], v);
        q = fmaf(a1.y, wq_[5], q); k = fmaf(a1.y, wk_[5], k); v = fmaf(a1.y, wv_[5], v);
        q = fmaf(a1.z, wq_[6], q); k = fmaf(a1.z, wk_[6], k); v = fmaf(a1.z, wv_[6], v);
        q = fmaf(a1.w, wq_[7], q); k = fmaf(a1.w, wk_[7], k); v = fmaf(a1.w, wv_[7], v);
#pragma unroll
        for (int o = 16; o > 0; o >>= 1) {
            q += __shfl_xor_sync(0xffffffffu, q, o);
            k += __shfl_xor_sync(0xffffffffu, k, o);
            v += __shfl_xor_sync(0xffffffffu, v, o);
        }
        float kk = k + cf1;
        lmax = fmaxf(lmax, kk); lmin = fminf(lmin, kk);
        if (lane == 0) {
            g_qs[b * N_ + p] = q + cf0;
            g_ks[b * N_ + p] = kk;
            g_vs[b * N_ + p] = v + cf2;
        }
    }
    if (lane == 0) {
        atomicMax(&g_kmax_u[b], encf(lmax));
        atomicMin(&g_kmin_u[b], encf(lmin));
    }
}

// ---------------------------------------------------------------------------
// K4: spatial softmax attention. grid (74, B), 256 thr (8 warps).
// k/v interleaved in SMEM; 4 query rows per warp amortize the LDS so the
// MUFU (EX2) pipe is the only binder.
// ---------------------------------------------------------------------------
__global__ void k_attn(float* __restrict__ out) {
    __shared__ float2 skv[N_];
    int b = blockIdx.y, t = threadIdx.x, lane = t & 31, wid = t >> 5;

    const float* kp = g_ks + b * N_;
    const float* vp = g_vs + b * N_;
    for (int i = t; i < N_; i += 256) skv[i] = make_float2(kp[i], vp[i]);
    __syncthreads();

    float kmx = decf(g_kmax_u[b]), kmn = decf(g_kmin_u[b]);
    int base = blockIdx.x * RPB;

    for (int r0 = wid * 4; r0 < RPB; r0 += 32) {
        int i0 = base + r0;
        float c1[4], mb[4], num[4], den[4];
#pragma unroll
        for (int s = 0; s < 4; s++) {
            int i = i0 + s;
            float qi = (i < N_) ? g_qs[b * N_ + i] : 0.f;
            float m  = (qi >= 0.f) ? qi * kmx : qi * kmn;
            c1[s] = qi * LOG2E; mb[s] = m * LOG2E;
            num[s] = 0.f; den[s] = 0.f;
        }
#pragma unroll 4
        for (int j = lane; j < N_; j += 32) {
            float2 kv = skv[j];
#pragma unroll
            for (int s = 0; s < 4; s++) {
                float e = ex2f(fmaf(c1[s], kv.x, -mb[s]));
                den[s] += e;
                num[s] = fmaf(e, kv.y, num[s]);
            }
        }
#pragma unroll
        for (int s = 0; s < 4; s++) {
            float n = num[s], d = den[s];
#pragma unroll
            for (int o = 16; o > 0; o >>= 1) {
                n += __shfl_xor_sync(0xffffffffu, n, o);
                d += __shfl_xor_sync(0xffffffffu, d, o);
            }
            int i = i0 + s;
            if (lane == 0 && i < N_) out[b * N_ + i] = skv[i].y + n / d;
        }
    }
}

// ---------------------------------------------------------------------------
extern "C" void kernel_launch(void* const* d_in, const int* in_sizes, int n_in,
                              void* d_out, int out_size) {
    const float* x    = (const float*)d_in[0];
    const float* ca_g = (const float*)d_in[1];
    const float* ca_b = (const float*)d_in[2];
    const float* ca_m = (const float*)d_in[3];
    const float* ca_v = (const float*)d_in[4];
    const float* wq   = (const float*)d_in[5];
    const float* wk   = (const float*)d_in[6];
    const float* wv   = (const float*)d_in[7];
    const float* wp   = (const float*)d_in[8];
    const float* bn_g = (const float*)d_in[9];
    const float* bn_b = (const float*)d_in[10];
    const float* bn_m = (const float*)d_in[11];
    const float* bn_v = (const float*)d_in[12];
    const float* wqkv = (const float*)d_in[13];
    float* out = (float*)d_out;

    k_gap_partial<<<dim3(CHUNKS, B_), C_>>>(x);
    k_channel<<<B_, C_>>>(ca_g, ca_b, ca_m, ca_v, wq, wk, wv, wp,
                          bn_g, bn_b, bn_m, bn_v, wqkv);
    k_qkv<<<dim3(32, B_), 256>>>(x);
    k_attn<<<dim3((N_ + RPB - 1) / RPB, B_), 256>>>(out);
}

// round 3
// speedup vs baseline: 2.0638x; 1.6089x over previous
#include <cuda_runtime.h>

#define C_    256
#define B_    4
#define N_    4096
#define EPSF  1e-3f
#define LOG2E 1.4426950408889634f
#define GCH   128   // gap partial chunks per batch
#define RPB   56    // rows per attention block (8 warps * 7 rows)

// ---- scratch (device globals, no allocations) ----
__device__ float g_partial[B_ * GCH * C_];
__device__ float g_wf[B_ * C_ * 3];
__device__ float g_cf[B_ * 3];
__device__ float g_qs[B_ * N_];
__device__ float g_ks[B_ * N_];
__device__ float g_vs[B_ * N_];
__device__ unsigned g_kmax_u[B_];
__device__ unsigned g_kmin_u[B_];

__device__ __forceinline__ float ex2f(float x) {
    float r;
    asm("ex2.approx.ftz.f32 %0, %1;" : "=f"(r) : "f"(x));
    return r;
}
__device__ __forceinline__ unsigned encf(float f) {
    unsigned u = __float_as_uint(f);
    return (u & 0x80000000u) ? ~u : (u | 0x80000000u);
}
__device__ __forceinline__ float decf(unsigned u) {
    return __uint_as_float((u & 0x80000000u) ? (u ^ 0x80000000u) : ~u);
}

// ---------------------------------------------------------------------------
// K1: GAP partials with float4 coalesced loads. grid (GCH, B), 256 thr.
// Block handles 32 rows; thread (c4 = t&63 float4-group, rs = t>>6 row-phase).
// ---------------------------------------------------------------------------
__global__ void k_gap(const float* __restrict__ x) {
    __shared__ float4 sh[4][64];
    int b = blockIdx.y, blk = blockIdx.x, t = threadIdx.x;
    if (blk == 0 && b == 0 && t < B_) {
        g_kmax_u[t] = 0u;
        g_kmin_u[t] = 0xffffffffu;
    }
    int c4 = t & 63, rs = t >> 6;
    const float4* xp = (const float4*)(x + (size_t)b * N_ * C_);
    float4 s = make_float4(0.f, 0.f, 0.f, 0.f);
#pragma unroll
    for (int i = 0; i < 8; i++) {
        int row = blk * 32 + rs + 4 * i;
        float4 a = xp[(size_t)row * 64 + c4];
        s.x += a.x; s.y += a.y; s.z += a.z; s.w += a.w;
    }
    sh[rs][c4] = s;
    __syncthreads();
    if (t < 64) {
        float4 a = sh[0][t], bb = sh[1][t], c = sh[2][t], d = sh[3][t];
        float4 r;
        r.x = a.x + bb.x + c.x + d.x;
        r.y = a.y + bb.y + c.y + d.y;
        r.z = a.z + bb.z + c.z + d.z;
        r.w = a.w + bb.w + c.w + d.w;
        ((float4*)(g_partial + (size_t)(b * GCH + blk) * C_))[t] = r;
    }
}

// ---------------------------------------------------------------------------
// K2: channel attention, 1024 threads, grid B.
// gap-final -> BN -> q/k/v matvec (float4 weights) -> spread softmax ->
// wp matvec -> sigmoid -> percentile -> fused qkv weights.
// ---------------------------------------------------------------------------
__global__ void __launch_bounds__(1024) k_channel(
        const float* __restrict__ ca_g, const float* __restrict__ ca_b,
        const float* __restrict__ ca_m, const float* __restrict__ ca_v,
        const float* __restrict__ wq,   const float* __restrict__ wk,
        const float* __restrict__ wv,   const float* __restrict__ wp,
        const float* __restrict__ bn_g, const float* __restrict__ bn_b,
        const float* __restrict__ bn_m, const float* __restrict__ bn_v,
        const float* __restrict__ wqkv) {
    __shared__ float4 red[16][65];                 // 16.6 KB scratch
    __shared__ float sh_gn[C_], sh_q[C_], sh_k[C_], sh_v[C_];
    __shared__ float sh_att[C_], sh_cm[C_], sh_d[C_];
    __shared__ float sh_mx[8], sh_mn[8], sh_scal[4];
    float* rbuf = (float*)red;                     // 4160 floats
    int*   ibuf = (int*)red;
    int b = blockIdx.x, t = threadIdx.x;
    int lane = t & 31, wid = t >> 5;
    int col = t & 255, seg = t >> 8;               // seg in 0..3
    int u = t & 63, r = t >> 6;                    // r in 0..15

    // ---- gap final + BN ----
    {
        float s = 0.f;
#pragma unroll 8
        for (int i = 0; i < 32; i++)
            s += g_partial[(size_t)(b * GCH + seg * 32 + i) * C_ + col];
        rbuf[t] = s;
    }
    __syncthreads();
    if (t < 256) {
        float gap = (rbuf[t] + rbuf[t + 256] + rbuf[t + 512] + rbuf[t + 768]) * (1.f / N_);
        sh_gn[t] = (gap - ca_m[t]) * rsqrtf(ca_v[t] + EPSF) * ca_g[t] + ca_b[t];
    }
    __syncthreads();

    // ---- q,k,v matvec: thread owns cols 4u..4u+3, rows r*16..r*16+15 ----
    float4 q4 = make_float4(0, 0, 0, 0), k4 = q4, v4 = q4;
#pragma unroll
    for (int i = 0; i < 16; i++) {
        int c = r * 16 + i;
        float g = sh_gn[c];
        float4 a = ((const float4*)(wq + (size_t)c * C_))[u];
        q4.x = fmaf(g, a.x, q4.x); q4.y = fmaf(g, a.y, q4.y);
        q4.z = fmaf(g, a.z, q4.z); q4.w = fmaf(g, a.w, q4.w);
        float4 bb = ((const float4*)(wk + (size_t)c * C_))[u];
        k4.x = fmaf(g, bb.x, k4.x); k4.y = fmaf(g, bb.y, k4.y);
        k4.z = fmaf(g, bb.z, k4.z); k4.w = fmaf(g, bb.w, k4.w);
        float4 cc = ((const float4*)(wv + (size_t)c * C_))[u];
        v4.x = fmaf(g, cc.x, v4.x); v4.y = fmaf(g, cc.y, v4.y);
        v4.z = fmaf(g, cc.z, v4.z); v4.w = fmaf(g, cc.w, v4.w);
    }
    __syncthreads();              // rbuf readers done
    red[r][u] = q4; __syncthreads();
    if (t < 256) {
        float s = 0.f;
#pragma unroll
        for (int rr = 0; rr < 16; rr++) s += ((const float*)&red[rr][t >> 2])[t & 3];
        sh_q[t] = s;
    }
    __syncthreads();
    red[r][u] = k4; __syncthreads();
    if (t < 256) {
        float s = 0.f;
#pragma unroll
        for (int rr = 0; rr < 16; rr++) s += ((const float*)&red[rr][t >> 2])[t & 3];
        sh_k[t] = s;
    }
    __syncthreads();
    red[r][u] = v4; __syncthreads();
    if (t < 256) {
        float s = 0.f;
#pragma unroll
        for (int rr = 0; rr < 16; rr++) s += ((const float*)&red[rr][t >> 2])[t & 3];
        sh_v[t] = s;
    }
    __syncthreads();

    // ---- k min/max ----
    if (t < 256) {
        float kk = sh_k[t];
        float mx = kk, mn = kk;
#pragma unroll
        for (int o = 16; o > 0; o >>= 1) {
            mx = fmaxf(mx, __shfl_xor_sync(0xffffffffu, mx, o));
            mn = fminf(mn, __shfl_xor_sync(0xffffffffu, mn, o));
        }
        if (lane == 0) { sh_mx[wid] = mx; sh_mn[wid] = mn; }
    }
    __syncthreads();
    if (t == 0) {
        float mx = sh_mx[0], mn = sh_mn[0];
        for (int i = 1; i < 8; i++) { mx = fmaxf(mx, sh_mx[i]); mn = fminf(mn, sh_mn[i]); }
        sh_scal[0] = mx; sh_scal[1] = mn;
    }
    __syncthreads();

    // ---- channel softmax, spread over 4 segments ----
    {
        float q = sh_q[col];
        float m = (q >= 0.f) ? q * sh_scal[0] : q * sh_scal[1];
        float c1 = q * LOG2E, mb = m * LOG2E;
        float num = 0.f, den = 0.f;
#pragma unroll 8
        for (int j = seg * 64; j < seg * 64 + 64; j++) {
            float e = ex2f(fmaf(c1, sh_k[j], -mb));
            den += e;
            num = fmaf(e, sh_v[j], num);
        }
        rbuf[t] = num; rbuf[2048 + t] = den;
    }
    __syncthreads();
    if (t < 256) {
        float num = rbuf[t] + rbuf[t + 256] + rbuf[t + 512] + rbuf[t + 768];
        float den = rbuf[2048 + t] + rbuf[2048 + t + 256] + rbuf[2048 + t + 512] + rbuf[2048 + t + 768];
        sh_att[t] = num / den;
    }
    __syncthreads();

    // ---- wp matvec ----
    float4 s4 = make_float4(0, 0, 0, 0);
#pragma unroll
    for (int i = 0; i < 16; i++) {
        int c = r * 16 + i;
        float g = sh_att[c];
        float4 a = ((const float4*)(wp + (size_t)c * C_))[u];
        s4.x = fmaf(g, a.x, s4.x); s4.y = fmaf(g, a.y, s4.y);
        s4.z = fmaf(g, a.z, s4.z); s4.w = fmaf(g, a.w, s4.w);
    }
    red[r][u] = s4; __syncthreads();
    if (t < 256) {
        float s = 0.f;
#pragma unroll
        for (int rr = 0; rr < 16; rr++) s += ((const float*)&red[rr][t >> 2])[t & 3];
        sh_cm[t] = 1.0f / (1.0f + ex2f(-s * LOG2E));
    }
    __syncthreads();

    // ---- percentile rank (pos 25.5 -> 0.5*(s[25]+s[26])), spread ----
    {
        float cm = sh_cm[col];
        int cnt = 0;
#pragma unroll 8
        for (int j = seg * 64; j < seg * 64 + 64; j++) {
            float cj = sh_cm[j];
            cnt += (cj < cm) || (cj == cm && j < col);
        }
        ibuf[t] = cnt;
    }
    __syncthreads();
    if (t < 256) {
        int rank = ibuf[t] + ibuf[t + 256] + ibuf[t + 512] + ibuf[t + 768];
        float cm = sh_cm[t];
        if (rank == 25) sh_scal[2] = cm;
        if (rank == 26) sh_scal[3] = cm;
    }
    __syncthreads();
    if (t < 256) {
        float cm  = sh_cm[t];
        float thr = 0.5f * (sh_scal[2] + sh_scal[3]);
        float pm  = (cm > thr) ? cm : 0.f;
        float rs  = rsqrtf(bn_v[t] + EPSF) * bn_g[t];
        float a   = (1.f + cm) * rs * pm;
        float d   = (bn_b[t] - bn_m[t] * rs) * pm;
#pragma unroll
        for (int f = 0; f < 3; f++) g_wf[(b * C_ + t) * 3 + f] = a * wqkv[t * 3 + f];
        sh_d[t] = d;
    }
    __syncthreads();
    if (t < 3) {
        float cf = 0.f;
        for (int c = 0; c < C_; c++) cf = fmaf(sh_d[c], wqkv[c * 3 + t], cf);
        g_cf[b * 3 + t] = cf;
    }
}

// ---------------------------------------------------------------------------
// K3: qkv projection, warp-per-pixel, spread over 296 blocks. grid (74, B).
// ---------------------------------------------------------------------------
__global__ void k_qkv(const float* __restrict__ x) {
    int b = blockIdx.y, t = threadIdx.x, lane = t & 31, wid = t >> 5;

    const float* wf = g_wf + b * C_ * 3;
    float wq_[8], wk_[8], wv_[8];
#pragma unroll
    for (int i = 0; i < 4; i++) {
        int c0 = 4 * lane + i, c1 = 128 + 4 * lane + i;
        wq_[i]     = wf[c0 * 3 + 0]; wk_[i]     = wf[c0 * 3 + 1]; wv_[i]     = wf[c0 * 3 + 2];
        wq_[4 + i] = wf[c1 * 3 + 0]; wk_[4 + i] = wf[c1 * 3 + 1]; wv_[4 + i] = wf[c1 * 3 + 2];
    }
    float cf0 = g_cf[b * 3 + 0], cf1 = g_cf[b * 3 + 1], cf2 = g_cf[b * 3 + 2];

    const float4* x4 = (const float4*)(x + (size_t)b * N_ * C_);
    int w = blockIdx.x * 8 + wid;          // 0..591
    float lmax = -1e30f, lmin = 1e30f;

#pragma unroll
    for (int i = 0; i < 7; i++) {
        int p = w + 592 * i;
        if (p < N_) {
            float4 a0 = x4[(size_t)p * 64 + lane];
            float4 a1 = x4[(size_t)p * 64 + 32 + lane];
            float q, k, v;
            q = a0.x * wq_[0]; k = a0.x * wk_[0]; v = a0.x * wv_[0];
            q = fmaf(a0.y, wq_[1], q); k = fmaf(a0.y, wk_[1], k); v = fmaf(a0.y, wv_[1], v);
            q = fmaf(a0.z, wq_[2], q); k = fmaf(a0.z, wk_[2], k); v = fmaf(a0.z, wv_[2], v);
            q = fmaf(a0.w, wq_[3], q); k = fmaf(a0.w, wk_[3], k); v = fmaf(a0.w, wv_[3], v);
            q = fmaf(a1.x, wq_[4], q); k = fmaf(a1.x, wk_[4], k); v = fmaf(a1.x, wv_[4], v);
            q = fmaf(a1.y, wq_[5], q); k = fmaf(a1.y, wk_[5], k); v = fmaf(a1.y, wv_[5], v);
            q = fmaf(a1.z, wq_[6], q); k = fmaf(a1.z, wk_[6], k); v = fmaf(a1.z, wv_[6], v);
            q = fmaf(a1.w, wq_[7], q); k = fmaf(a1.w, wk_[7], k); v = fmaf(a1.w, wv_[7], v);
#pragma unroll
            for (int o = 16; o > 0; o >>= 1) {
                q += __shfl_xor_sync(0xffffffffu, q, o);
                k += __shfl_xor_sync(0xffffffffu, k, o);
                v += __shfl_xor_sync(0xffffffffu, v, o);
            }
            float kk = k + cf1;
            lmax = fmaxf(lmax, kk); lmin = fminf(lmin, kk);
            if (lane == 0) {
                g_qs[b * N_ + p] = q + cf0;
                g_ks[b * N_ + p] = kk;
                g_vs[b * N_ + p] = v + cf2;
            }
        }
    }
    if (lane == 0) {
        atomicMax(&g_kmax_u[b], encf(lmax));
        atomicMin(&g_kmin_u[b], encf(lmin));
    }
}

// ---------------------------------------------------------------------------
// K4: spatial softmax attention. grid (74, B) = 296 blocks (exactly 2/SM),
// 8 warps * 7 rows = 56 rows/block, perfectly balanced.
// Rows 0-5 use MUFU EX2; row 6 uses an FMA-pipe polynomial exp2.
// ---------------------------------------------------------------------------
__global__ void k_attn(float* __restrict__ out) {
    __shared__ float2 skv[N_];
    int b = blockIdx.y, t = threadIdx.x, lane = t & 31, wid = t >> 5;

    const float* kp = g_ks + b * N_;
    const float* vp = g_vs + b * N_;
    for (int i = t; i < N_; i += 256) skv[i] = make_float2(kp[i], vp[i]);
    __syncthreads();

    float kmx = decf(g_kmax_u[b]), kmn = decf(g_kmin_u[b]);
    int i0 = blockIdx.x * RPB + wid * 7;

    float c1[7], mb[7], num[7], den[7];
#pragma unroll
    for (int s = 0; s < 7; s++) {
        int i = i0 + s;
        float qi = (i < N_) ? g_qs[b * N_ + i] : 0.f;
        float m  = (qi >= 0.f) ? qi * kmx : qi * kmn;
        c1[s] = qi * LOG2E; mb[s] = m * LOG2E;
        num[s] = 0.f; den[s] = 0.f;
    }

#pragma unroll 2
    for (int j = lane; j < N_; j += 32) {
        float2 kv = skv[j];
#pragma unroll
        for (int s = 0; s < 6; s++) {
            float e = ex2f(fmaf(c1[s], kv.x, -mb[s]));
            den[s] += e;
            num[s] = fmaf(e, kv.y, num[s]);
        }
        // row 6: polynomial exp2 on the fma pipe
        float x6 = fmaf(c1[6], kv.x, -mb[6]);
        x6 = fmaxf(x6, -126.f);
        float z  = __fadd_rn(x6, 12582912.f);           // round-to-nearest int
        int   ii = __float_as_int(z) << 23;
        float fr = __fsub_rn(x6, __fsub_rn(z, 12582912.f));  // in [-0.5, 0.5]
        float pl = fmaf(fr, 1.3333558e-3f, 9.6181291e-3f);
        pl = fmaf(fr, pl, 5.5504109e-2f);
        pl = fmaf(fr, pl, 2.4022651e-1f);
        pl = fmaf(fr, pl, 6.9314718e-1f);
        pl = fmaf(fr, pl, 1.0f);
        float e6 = __int_as_float(__float_as_int(pl) + ii);
        den[6] += e6;
        num[6] = fmaf(e6, kv.y, num[6]);
    }

#pragma unroll
    for (int s = 0; s < 7; s++) {
        float n = num[s], d = den[s];
#pragma unroll
        for (int o = 16; o > 0; o >>= 1) {
            n += __shfl_xor_sync(0xffffffffu, n, o);
            d += __shfl_xor_sync(0xffffffffu, d, o);
        }
        int i = i0 + s;
        if (lane == 0 && i < N_) out[b * N_ + i] = skv[i].y + n / d;
    }
}

// ---------------------------------------------------------------------------
extern "C" void kernel_launch(void* const* d_in, const int* in_sizes, int n_in,
                              void* d_out, int out_size) {
    const float* x    = (const float*)d_in[0];
    const float* ca_g = (const float*)d_in[1];
    const float* ca_b = (const float*)d_in[2];
    const float* ca_m = (const float*)d_in[3];
    const float* ca_v = (const float*)d_in[4];
    const float* wq   = (const float*)d_in[5];
    const float* wk   = (const float*)d_in[6];
    const float* wv   = (const float*)d_in[7];
    const float* wp   = (const float*)d_in[8];
    const float* bn_g = (const float*)d_in[9];
    const float* bn_b = (const float*)d_in[10];
    const float* bn_m = (const float*)d_in[11];
    const float* bn_v = (const float*)d_in[12];
    const float* wqkv = (const float*)d_in[13];
    float* out = (float*)d_out;

    k_gap<<<dim3(GCH, B_), 256>>>(x);
    k_channel<<<B_, 1024>>>(ca_g, ca_b, ca_m, ca_v, wq, wk, wv, wp,
                            bn_g, bn_b, bn_m, bn_v, wqkv);
    k_qkv<<<dim3(74, B_), 256>>>(x);
    k_attn<<<dim3(74, B_), 256>>>(out);
}

// round 4
// speedup vs baseline: 2.2509x; 1.0907x over previous
#include <cuda_runtime.h>

#define C_    256
#define B_    4
#define N_    4096
#define EPSF  1e-3f
#define LOG2E 1.4426950408889634f
#define GCH   128   // gap partial chunks per batch
#define RPB   28    // rows per attention block (4 warps*4 + 4 warps*3)

// ---- scratch (device globals, no allocations) ----
__device__ float g_partial[B_ * GCH * C_];
__device__ float g_wf[B_ * C_ * 3];
__device__ float g_cf[B_ * 3];
__device__ float g_qs[B_ * N_];
__device__ float g_ks[B_ * N_];
__device__ float g_vs[B_ * N_];
__device__ unsigned g_kmax_u[B_];
__device__ unsigned g_kmin_u[B_];

__device__ __forceinline__ float ex2f(float x) {
    float r;
    asm("ex2.approx.ftz.f32 %0, %1;" : "=f"(r) : "f"(x));
    return r;
}
__device__ __forceinline__ unsigned encf(float f) {
    unsigned u = __float_as_uint(f);
    return (u & 0x80000000u) ? ~u : (u | 0x80000000u);
}
__device__ __forceinline__ float decf(unsigned u) {
    return __uint_as_float((u & 0x80000000u) ? (u ^ 0x80000000u) : ~u);
}

// ---------------------------------------------------------------------------
// K1: GAP partials with float4 coalesced loads. grid (GCH, B), 256 thr.
// ---------------------------------------------------------------------------
__global__ void k_gap(const float* __restrict__ x) {
    __shared__ float4 sh[4][64];
    int b = blockIdx.y, blk = blockIdx.x, t = threadIdx.x;
    if (blk == 0 && b == 0 && t < B_) {
        g_kmax_u[t] = 0u;
        g_kmin_u[t] = 0xffffffffu;
    }
    int c4 = t & 63, rs = t >> 6;
    const float4* xp = (const float4*)(x + (size_t)b * N_ * C_);
    float4 s = make_float4(0.f, 0.f, 0.f, 0.f);
#pragma unroll
    for (int i = 0; i < 8; i++) {
        int row = blk * 32 + rs + 4 * i;
        float4 a = xp[(size_t)row * 64 + c4];
        s.x += a.x; s.y += a.y; s.z += a.z; s.w += a.w;
    }
    sh[rs][c4] = s;
    __syncthreads();
    if (t < 64) {
        float4 a = sh[0][t], bb = sh[1][t], c = sh[2][t], d = sh[3][t];
        float4 r;
        r.x = a.x + bb.x + c.x + d.x;
        r.y = a.y + bb.y + c.y + d.y;
        r.z = a.z + bb.z + c.z + d.z;
        r.w = a.w + bb.w + c.w + d.w;
        ((float4*)(g_partial + (size_t)(b * GCH + blk) * C_))[t] = r;
    }
}

// ---------------------------------------------------------------------------
// K2: channel attention, 1024 threads, grid B.
// ---------------------------------------------------------------------------
__global__ void __launch_bounds__(1024) k_channel(
        const float* __restrict__ ca_g, const float* __restrict__ ca_b,
        const float* __restrict__ ca_m, const float* __restrict__ ca_v,
        const float* __restrict__ wq,   const float* __restrict__ wk,
        const float* __restrict__ wv,   const float* __restrict__ wp,
        const float* __restrict__ bn_g, const float* __restrict__ bn_b,
        const float* __restrict__ bn_m, const float* __restrict__ bn_v,
        const float* __restrict__ wqkv) {
    __shared__ float4 red[16][65];
    __shared__ float sh_gn[C_], sh_q[C_], sh_k[C_], sh_v[C_];
    __shared__ float sh_att[C_], sh_cm[C_], sh_d[C_];
    __shared__ float sh_mx[8], sh_mn[8], sh_scal[4];
    float* rbuf = (float*)red;
    int*   ibuf = (int*)red;
    int b = blockIdx.x, t = threadIdx.x;
    int lane = t & 31, wid = t >> 5;
    int col = t & 255, seg = t >> 8;
    int u = t & 63, r = t >> 6;

    // ---- gap final + BN ----
    {
        float s = 0.f;
#pragma unroll 8
        for (int i = 0; i < 32; i++)
            s += g_partial[(size_t)(b * GCH + seg * 32 + i) * C_ + col];
        rbuf[t] = s;
    }
    __syncthreads();
    if (t < 256) {
        float gap = (rbuf[t] + rbuf[t + 256] + rbuf[t + 512] + rbuf[t + 768]) * (1.f / N_);
        sh_gn[t] = (gap - ca_m[t]) * rsqrtf(ca_v[t] + EPSF) * ca_g[t] + ca_b[t];
    }
    __syncthreads();

    // ---- q,k,v matvec ----
    float4 q4 = make_float4(0, 0, 0, 0), k4 = q4, v4 = q4;
#pragma unroll
    for (int i = 0; i < 16; i++) {
        int c = r * 16 + i;
        float g = sh_gn[c];
        float4 a = ((const float4*)(wq + (size_t)c * C_))[u];
        q4.x = fmaf(g, a.x, q4.x); q4.y = fmaf(g, a.y, q4.y);
        q4.z = fmaf(g, a.z, q4.z); q4.w = fmaf(g, a.w, q4.w);
        float4 bb = ((const float4*)(wk + (size_t)c * C_))[u];
        k4.x = fmaf(g, bb.x, k4.x); k4.y = fmaf(g, bb.y, k4.y);
        k4.z = fmaf(g, bb.z, k4.z); k4.w = fmaf(g, bb.w, k4.w);
        float4 cc = ((const float4*)(wv + (size_t)c * C_))[u];
        v4.x = fmaf(g, cc.x, v4.x); v4.y = fmaf(g, cc.y, v4.y);
        v4.z = fmaf(g, cc.z, v4.z); v4.w = fmaf(g, cc.w, v4.w);
    }
    __syncthreads();
    red[r][u] = q4; __syncthreads();
    if (t < 256) {
        float s = 0.f;
#pragma unroll
        for (int rr = 0; rr < 16; rr++) s += ((const float*)&red[rr][t >> 2])[t & 3];
        sh_q[t] = s;
    }
    __syncthreads();
    red[r][u] = k4; __syncthreads();
    if (t < 256) {
        float s = 0.f;
#pragma unroll
        for (int rr = 0; rr < 16; rr++) s += ((const float*)&red[rr][t >> 2])[t & 3];
        sh_k[t] = s;
    }
    __syncthreads();
    red[r][u] = v4; __syncthreads();
    if (t < 256) {
        float s = 0.f;
#pragma unroll
        for (int rr = 0; rr < 16; rr++) s += ((const float*)&red[rr][t >> 2])[t & 3];
        sh_v[t] = s;
    }
    __syncthreads();

    // ---- k min/max ----
    if (t < 256) {
        float kk = sh_k[t];
        float mx = kk, mn = kk;
#pragma unroll
        for (int o = 16; o > 0; o >>= 1) {
            mx = fmaxf(mx, __shfl_xor_sync(0xffffffffu, mx, o));
            mn = fminf(mn, __shfl_xor_sync(0xffffffffu, mn, o));
        }
        if (lane == 0) { sh_mx[wid] = mx; sh_mn[wid] = mn; }
    }
    __syncthreads();
    if (t == 0) {
        float mx = sh_mx[0], mn = sh_mn[0];
        for (int i = 1; i < 8; i++) { mx = fmaxf(mx, sh_mx[i]); mn = fminf(mn, sh_mn[i]); }
        sh_scal[0] = mx; sh_scal[1] = mn;
    }
    __syncthreads();

    // ---- channel softmax, spread over 4 segments ----
    {
        float q = sh_q[col];
        float m = (q >= 0.f) ? q * sh_scal[0] : q * sh_scal[1];
        float c1 = q * LOG2E, mb = m * LOG2E;
        float num = 0.f, den = 0.f;
#pragma unroll 8
        for (int j = seg * 64; j < seg * 64 + 64; j++) {
            float e = ex2f(fmaf(c1, sh_k[j], -mb));
            den += e;
            num = fmaf(e, sh_v[j], num);
        }
        rbuf[t] = num; rbuf[2048 + t] = den;
    }
    __syncthreads();
    if (t < 256) {
        float num = rbuf[t] + rbuf[t + 256] + rbuf[t + 512] + rbuf[t + 768];
        float den = rbuf[2048 + t] + rbuf[2048 + t + 256] + rbuf[2048 + t + 512] + rbuf[2048 + t + 768];
        sh_att[t] = num / den;
    }
    __syncthreads();

    // ---- wp matvec ----
    float4 s4 = make_float4(0, 0, 0, 0);
#pragma unroll
    for (int i = 0; i < 16; i++) {
        int c = r * 16 + i;
        float g = sh_att[c];
        float4 a = ((const float4*)(wp + (size_t)c * C_))[u];
        s4.x = fmaf(g, a.x, s4.x); s4.y = fmaf(g, a.y, s4.y);
        s4.z = fmaf(g, a.z, s4.z); s4.w = fmaf(g, a.w, s4.w);
    }
    red[r][u] = s4; __syncthreads();
    if (t < 256) {
        float s = 0.f;
#pragma unroll
        for (int rr = 0; rr < 16; rr++) s += ((const float*)&red[rr][t >> 2])[t & 3];
        sh_cm[t] = 1.0f / (1.0f + ex2f(-s * LOG2E));
    }
    __syncthreads();

    // ---- percentile rank (pos 25.5 -> 0.5*(s[25]+s[26])) ----
    {
        float cm = sh_cm[col];
        int cnt = 0;
#pragma unroll 8
        for (int j = seg * 64; j < seg * 64 + 64; j++) {
            float cj = sh_cm[j];
            cnt += (cj < cm) || (cj == cm && j < col);
        }
        ibuf[t] = cnt;
    }
    __syncthreads();
    if (t < 256) {
        int rank = ibuf[t] + ibuf[t + 256] + ibuf[t + 512] + ibuf[t + 768];
        float cm = sh_cm[t];
        if (rank == 25) sh_scal[2] = cm;
        if (rank == 26) sh_scal[3] = cm;
    }
    __syncthreads();
    if (t < 256) {
        float cm  = sh_cm[t];
        float thr = 0.5f * (sh_scal[2] + sh_scal[3]);
        float pm  = (cm > thr) ? cm : 0.f;
        float rs  = rsqrtf(bn_v[t] + EPSF) * bn_g[t];
        float a   = (1.f + cm) * rs * pm;
        float d   = (bn_b[t] - bn_m[t] * rs) * pm;
#pragma unroll
        for (int f = 0; f < 3; f++) g_wf[(b * C_ + t) * 3 + f] = a * wqkv[t * 3 + f];
        sh_d[t] = d;
    }
    __syncthreads();
    if (t < 3) {
        float cf = 0.f;
        for (int c = 0; c < C_; c++) cf = fmaf(sh_d[c], wqkv[c * 3 + t], cf);
        g_cf[b * 3 + t] = cf;
    }
}

// ---------------------------------------------------------------------------
// K3: qkv projection, warp-per-pixel. grid (74, B), 256 thr.
// ---------------------------------------------------------------------------
__global__ void k_qkv(const float* __restrict__ x) {
    int b = blockIdx.y, t = threadIdx.x, lane = t & 31, wid = t >> 5;

    const float* wf = g_wf + b * C_ * 3;
    float wq_[8], wk_[8], wv_[8];
#pragma unroll
    for (int i = 0; i < 4; i++) {
        int c0 = 4 * lane + i, c1 = 128 + 4 * lane + i;
        wq_[i]     = wf[c0 * 3 + 0]; wk_[i]     = wf[c0 * 3 + 1]; wv_[i]     = wf[c0 * 3 + 2];
        wq_[4 + i] = wf[c1 * 3 + 0]; wk_[4 + i] = wf[c1 * 3 + 1]; wv_[4 + i] = wf[c1 * 3 + 2];
    }
    float cf0 = g_cf[b * 3 + 0], cf1 = g_cf[b * 3 + 1], cf2 = g_cf[b * 3 + 2];

    const float4* x4 = (const float4*)(x + (size_t)b * N_ * C_);
    int w = blockIdx.x * 8 + wid;
    float lmax = -1e30f, lmin = 1e30f;

#pragma unroll
    for (int i = 0; i < 7; i++) {
        int p = w + 592 * i;
        if (p < N_) {
            float4 a0 = x4[(size_t)p * 64 + lane];
            float4 a1 = x4[(size_t)p * 64 + 32 + lane];
            float q, k, v;
            q = a0.x * wq_[0]; k = a0.x * wk_[0]; v = a0.x * wv_[0];
            q = fmaf(a0.y, wq_[1], q); k = fmaf(a0.y, wk_[1], k); v = fmaf(a0.y, wv_[1], v);
            q = fmaf(a0.z, wq_[2], q); k = fmaf(a0.z, wk_[2], k); v = fmaf(a0.z, wv_[2], v);
            q = fmaf(a0.w, wq_[3], q); k = fmaf(a0.w, wk_[3], k); v = fmaf(a0.w, wv_[3], v);
            q = fmaf(a1.x, wq_[4], q); k = fmaf(a1.x, wk_[4], k); v = fmaf(a1.x, wv_[4], v);
            q = fmaf(a1.y, wq_[5], q); k = fmaf(a1.y, wk_[5], k); v = fmaf(a1.y, wv_[5], v);
            q = fmaf(a1.z, wq_[6], q); k = fmaf(a1.z, wk_[6], k); v = fmaf(a1.z, wv_[6], v);
            q = fmaf(a1.w, wq_[7], q); k = fmaf(a1.w, wk_[7], k); v = fmaf(a1.w, wv_[7], v);
#pragma unroll
            for (int o = 16; o > 0; o >>= 1) {
                q += __shfl_xor_sync(0xffffffffu, q, o);
                k += __shfl_xor_sync(0xffffffffu, k, o);
                v += __shfl_xor_sync(0xffffffffu, v, o);
            }
            float kk = k + cf1;
            lmax = fmaxf(lmax, kk); lmin = fminf(lmin, kk);
            if (lane == 0) {
                g_qs[b * N_ + p] = q + cf0;
                g_ks[b * N_ + p] = kk;
                g_vs[b * N_ + p] = v + cf2;
            }
        }
    }
    if (lane == 0) {
        atomicMax(&g_kmax_u[b], encf(lmax));
        atomicMin(&g_kmin_u[b], encf(lmin));
    }
}

// ---------------------------------------------------------------------------
// K4: spatial softmax attention. grid (147, B) = 588 blocks (4/SM), 256 thr.
// Warps 0-3: 4 rows, warps 4-7: 3 rows (28 rows/block, SMSP-balanced).
// All-MUFU inner loop at minimal 4 instrs/exp; k/v packed as float4 pairs.
// ---------------------------------------------------------------------------
template <int NR>
__device__ __forceinline__ void attn_rows(const float4* skv4, int lane, int b, int i0,
                                          float kmx, float kmn, float* __restrict__ out) {
    float c1[NR], mb[NR], num[NR], den[NR], num2[NR], den2[NR];
#pragma unroll
    for (int s = 0; s < NR; s++) {
        int i = i0 + s;
        float qi = g_qs[b * N_ + ((i < N_) ? i : (N_ - 1))];
        float m  = (qi >= 0.f) ? qi * kmx : qi * kmn;
        c1[s] = qi * LOG2E; mb[s] = m * LOG2E;
        num[s] = 0.f; den[s] = 0.f; num2[s] = 0.f; den2[s] = 0.f;
    }
#pragma unroll 2
    for (int p = lane; p < N_ / 2; p += 32) {
        float4 kv = skv4[p];
#pragma unroll
        for (int s = 0; s < NR; s++) {
            float e0 = ex2f(fmaf(c1[s], kv.x, -mb[s]));
            den[s] += e0;
            num[s] = fmaf(e0, kv.y, num[s]);
            float e1 = ex2f(fmaf(c1[s], kv.z, -mb[s]));
            den2[s] += e1;
            num2[s] = fmaf(e1, kv.w, num2[s]);
        }
    }
#pragma unroll
    for (int s = 0; s < NR; s++) {
        float n = num[s] + num2[s], d = den[s] + den2[s];
#pragma unroll
        for (int o = 16; o > 0; o >>= 1) {
            n += __shfl_xor_sync(0xffffffffu, n, o);
            d += __shfl_xor_sync(0xffffffffu, d, o);
        }
        int i = i0 + s;
        if (lane == 0 && i < N_) out[b * N_ + i] = g_vs[b * N_ + i] + n / d;
    }
}

__global__ void __launch_bounds__(256) k_attn(float* __restrict__ out) {
    __shared__ float4 skv4[N_ / 2];
    int b = blockIdx.y, t = threadIdx.x, lane = t & 31, wid = t >> 5;

    const float2* kp = (const float2*)(g_ks + b * N_);
    const float2* vp = (const float2*)(g_vs + b * N_);
    for (int p = t; p < N_ / 2; p += 256) {
        float2 k2 = kp[p], v2 = vp[p];
        skv4[p] = make_float4(k2.x, v2.x, k2.y, v2.y);
    }
    __syncthreads();

    float kmx = decf(g_kmax_u[b]), kmn = decf(g_kmin_u[b]);
    int base = blockIdx.x * RPB;

    if (wid < 4)
        attn_rows<4>(skv4, lane, b, base + wid * 4, kmx, kmn, out);
    else
        attn_rows<3>(skv4, lane, b, base + 16 + (wid - 4) * 3, kmx, kmn, out);
}

// ---------------------------------------------------------------------------
extern "C" void kernel_launch(void* const* d_in, const int* in_sizes, int n_in,
                              void* d_out, int out_size) {
    const float* x    = (const float*)d_in[0];
    const float* ca_g = (const float*)d_in[1];
    const float* ca_b = (const float*)d_in[2];
    const float* ca_m = (const float*)d_in[3];
    const float* ca_v = (const float*)d_in[4];
    const float* wq   = (const float*)d_in[5];
    const float* wk   = (const float*)d_in[6];
    const float* wv   = (const float*)d_in[7];
    const float* wp   = (const float*)d_in[8];
    const float* bn_g = (const float*)d_in[9];
    const float* bn_b = (const float*)d_in[10];
    const float* bn_m = (const float*)d_in[11];
    const float* bn_v = (const float*)d_in[12];
    const float* wqkv = (const float*)d_in[13];
    float* out = (float*)d_out;

    k_gap<<<dim3(GCH, B_), 256>>>(x);
    k_channel<<<B_, 1024>>>(ca_g, ca_b, ca_m, ca_v, wq, wk, wv, wp,
                            bn_g, bn_b, bn_m, bn_v, wqkv);
    k_qkv<<<dim3(74, B_), 256>>>(x);
    k_attn<<<dim3((N_ + RPB - 1) / RPB, B_), 256>>>(out);
}

// round 6
// speedup vs baseline: 2.3551x; 1.0463x over previous
#include <cuda_runtime.h>

#define C_    256
#define B_    4
#define N_    4096
#define EPSF  1e-3f
#define LOG2E 1.4426950408889634f
#define GCH   128    // gap partial chunks per batch
#define ABL   111    // attention blocks per batch (111*37 >= 4096, 444 = 148*3)
#define ARPB  37     // attention rows per block

// ---- scratch (device globals, no allocations) ----
__device__ float g_partial[B_ * GCH * C_];
__device__ float g_mv[B_ * 16 * 3 * C_];    // matvec partials [b][seg][m][c]
__device__ float g_wf[B_ * C_ * 3];
__device__ float g_cf[B_ * 3];
__device__ float g_qs[B_ * N_];
__device__ float g_ks[B_ * N_];
__device__ float g_vs[B_ * N_];
__device__ unsigned g_kmax_u[B_];
__device__ unsigned g_kmin_u[B_];

__device__ __forceinline__ float ex2f(float x) {
    float r;
    asm("ex2.approx.ftz.f32 %0, %1;" : "=f"(r) : "f"(x));
    return r;
}
__device__ __forceinline__ unsigned encf(float f) {
    unsigned u = __float_as_uint(f);
    return (u & 0x80000000u) ? ~u : (u | 0x80000000u);
}
__device__ __forceinline__ float decf(unsigned u) {
    return __uint_as_float((u & 0x80000000u) ? (u ^ 0x80000000u) : ~u);
}

// ---------------------------------------------------------------------------
// K1: GAP partials with float4 coalesced loads. grid (GCH, B), 256 thr.
// ---------------------------------------------------------------------------
__global__ void k_gap(const float* __restrict__ x) {
    __shared__ float4 sh[4][64];
    int b = blockIdx.y, blk = blockIdx.x, t = threadIdx.x;
    if (blk == 0 && b == 0 && t < B_) {
        g_kmax_u[t] = 0u;
        g_kmin_u[t] = 0xffffffffu;
    }
    int c4 = t & 63, rs = t >> 6;
    const float4* xp = (const float4*)(x + (size_t)b * N_ * C_);
    float4 s = make_float4(0.f, 0.f, 0.f, 0.f);
#pragma unroll
    for (int i = 0; i < 8; i++) {
        int row = blk * 32 + rs + 4 * i;
        float4 a = xp[(size_t)row * 64 + c4];
        s.x += a.x; s.y += a.y; s.z += a.z; s.w += a.w;
    }
    sh[rs][c4] = s;
    __syncthreads();
    if (t < 64) {
        float4 a = sh[0][t], bb = sh[1][t], c = sh[2][t], d = sh[3][t];
        float4 r;
        r.x = a.x + bb.x + c.x + d.x;
        r.y = a.y + bb.y + c.y + d.y;
        r.z = a.z + bb.z + c.z + d.z;
        r.w = a.w + bb.w + c.w + d.w;
        ((float4*)(g_partial + (size_t)(b * GCH + blk) * C_))[t] = r;
    }
}

// ---------------------------------------------------------------------------
// K2: gap-final + BN + q/k/v matvec PARTIALS. grid (16, B), 256 thr.
// Block (seg, b): owns 16 channel-rows [seg*16, +16); writes partial rows
// of q/k/v (length 256) to g_mv. 64 blocks spread the 768KB weight read.
// ---------------------------------------------------------------------------
__global__ void __launch_bounds__(256) k_mv(
        const float* __restrict__ ca_g, const float* __restrict__ ca_b,
        const float* __restrict__ ca_m, const float* __restrict__ ca_v,
        const float* __restrict__ wq,   const float* __restrict__ wk,
        const float* __restrict__ wv) {
    __shared__ float4 red[4][65];
    __shared__ float sh_gn[16];
    int seg = blockIdx.x, b = blockIdx.y, t = threadIdx.x;
    int u = t & 63, r2 = t >> 6;
    float* rb = (float*)red;

    // gap final for this segment's 16 channels: thread (c_l, piece)
    {
        int c_l = t >> 4, piece = t & 15;
        float s = 0.f;
#pragma unroll
        for (int j = 0; j < 8; j++)
            s += g_partial[(size_t)(b * GCH + piece * 8 + j) * C_ + seg * 16 + c_l];
        rb[c_l * 16 + piece] = s;
    }
    __syncthreads();
    if (t < 16) {
        float ss = 0.f;
#pragma unroll
        for (int p = 0; p < 16; p++) ss += rb[t * 16 + p];
        float gap = ss * (1.f / N_);
        int c = seg * 16 + t;
        sh_gn[t] = (gap - ca_m[c]) * rsqrtf(ca_v[c] + EPSF) * ca_g[c] + ca_b[c];
    }
    __syncthreads();

    // matvec partials over 16 channel-rows; thread owns cols 4u..4u+3
    float4 q4 = make_float4(0, 0, 0, 0), k4 = q4, v4 = q4;
#pragma unroll
    for (int i = 0; i < 4; i++) {
        int cl = r2 * 4 + i;
        int c  = seg * 16 + cl;
        float gg = sh_gn[cl];
        float4 a = ((const float4*)(wq + (size_t)c * C_))[u];
        q4.x = fmaf(gg, a.x, q4.x); q4.y = fmaf(gg, a.y, q4.y);
        q4.z = fmaf(gg, a.z, q4.z); q4.w = fmaf(gg, a.w, q4.w);
        float4 bb = ((const float4*)(wk + (size_t)c * C_))[u];
        k4.x = fmaf(gg, bb.x, k4.x); k4.y = fmaf(gg, bb.y, k4.y);
        k4.z = fmaf(gg, bb.z, k4.z); k4.w = fmaf(gg, bb.w, k4.w);
        float4 cc = ((const float4*)(wv + (size_t)c * C_))[u];
        v4.x = fmaf(gg, cc.x, v4.x); v4.y = fmaf(gg, cc.y, v4.y);
        v4.z = fmaf(gg, cc.z, v4.z); v4.w = fmaf(gg, cc.w, v4.w);
    }
    float* mv = g_mv + (size_t)(b * 16 + seg) * 3 * C_;
    __syncthreads();
    red[r2][u] = q4; __syncthreads();
    if (t < 64) {
        float4 a = red[0][t], bb = red[1][t], c = red[2][t], d = red[3][t];
        ((float4*)mv)[t] = make_float4(a.x + bb.x + c.x + d.x, a.y + bb.y + c.y + d.y,
                                       a.z + bb.z + c.z + d.z, a.w + bb.w + c.w + d.w);
    }
    __syncthreads();
    red[r2][u] = k4; __syncthreads();
    if (t < 64) {
        float4 a = red[0][t], bb = red[1][t], c = red[2][t], d = red[3][t];
        ((float4*)(mv + C_))[t] = make_float4(a.x + bb.x + c.x + d.x, a.y + bb.y + c.y + d.y,
                                              a.z + bb.z + c.z + d.z, a.w + bb.w + c.w + d.w);
    }
    __syncthreads();
    red[r2][u] = v4; __syncthreads();
    if (t < 64) {
        float4 a = red[0][t], bb = red[1][t], c = red[2][t], d = red[3][t];
        ((float4*)(mv + 2 * C_))[t] = make_float4(a.x + bb.x + c.x + d.x, a.y + bb.y + c.y + d.y,
                                                  a.z + bb.z + c.z + d.z, a.w + bb.w + c.w + d.w);
    }
}

// ---------------------------------------------------------------------------
// K3: finalize channel attention. grid B, 1024 thr.
// Reduce matvec partials -> channel softmax -> wp matvec -> sigmoid ->
// percentile -> fused qkv weights.
// ---------------------------------------------------------------------------
__global__ void __launch_bounds__(1024) k_fin(
        const float* __restrict__ wp,
        const float* __restrict__ bn_g, const float* __restrict__ bn_b,
        const float* __restrict__ bn_m, const float* __restrict__ bn_v,
        const float* __restrict__ wqkv) {
    __shared__ float4 red[16][65];
    __shared__ float sh_q[C_], sh_k[C_], sh_v[C_];
    __shared__ float sh_att[C_], sh_cm[C_], sh_d[C_];
    __shared__ float sh_mx[8], sh_mn[8], sh_scal[4];
    float* rbuf = (float*)red;
    int*   ibuf = (int*)red;
    int b = blockIdx.x, t = threadIdx.x;
    int lane = t & 31, wid = t >> 5;
    int col = t & 255, seg = t >> 8;
    int u = t & 63, r = t >> 6;

    // ---- reduce q/k/v partials over 16 segments, spread over 4 ----
    {
        float qf = 0.f, kf = 0.f, vf = 0.f;
#pragma unroll
        for (int s2 = 0; s2 < 4; s2++) {
            const float* mv = g_mv + (size_t)(b * 16 + seg * 4 + s2) * 3 * C_;
            qf += mv[col]; kf += mv[C_ + col]; vf += mv[2 * C_ + col];
        }
        rbuf[t] = qf; rbuf[1024 + t] = kf; rbuf[2048 + t] = vf;
    }
    __syncthreads();
    if (t < 256) {
        sh_q[t] = rbuf[t] + rbuf[t + 256] + rbuf[t + 512] + rbuf[t + 768];
        sh_k[t] = rbuf[1024 + t] + rbuf[1024 + t + 256] + rbuf[1024 + t + 512] + rbuf[1024 + t + 768];
        sh_v[t] = rbuf[2048 + t] + rbuf[2048 + t + 256] + rbuf[2048 + t + 512] + rbuf[2048 + t + 768];
    }
    __syncthreads();

    // ---- k min/max ----
    if (t < 256) {
        float kk = sh_k[t];
        float mx = kk, mn = kk;
#pragma unroll
        for (int o = 16; o > 0; o >>= 1) {
            mx = fmaxf(mx, __shfl_xor_sync(0xffffffffu, mx, o));
            mn = fminf(mn, __shfl_xor_sync(0xffffffffu, mn, o));
        }
        if (lane == 0) { sh_mx[wid] = mx; sh_mn[wid] = mn; }
    }
    __syncthreads();
    if (t == 0) {
        float mx = sh_mx[0], mn = sh_mn[0];
        for (int i = 1; i < 8; i++) { mx = fmaxf(mx, sh_mx[i]); mn = fminf(mn, sh_mn[i]); }
        sh_scal[0] = mx; sh_scal[1] = mn;
    }
    __syncthreads();

    // ---- channel softmax, spread over 4 segments ----
    {
        float q = sh_q[col];
        float m = (q >= 0.f) ? q * sh_scal[0] : q * sh_scal[1];
        float c1 = q * LOG2E, mb = m * LOG2E;
        float num = 0.f, den = 0.f;
#pragma unroll 8
        for (int j = seg * 64; j < seg * 64 + 64; j++) {
            float e = ex2f(fmaf(c1, sh_k[j], -mb));
            den += e;
            num = fmaf(e, sh_v[j], num);
        }
        rbuf[t] = num; rbuf[2048 + t] = den;
    }
    __syncthreads();
    if (t < 256) {
        float num = rbuf[t] + rbuf[t + 256] + rbuf[t + 512] + rbuf[t + 768];
        float den = rbuf[2048 + t] + rbuf[2048 + t + 256] + rbuf[2048 + t + 512] + rbuf[2048 + t + 768];
        sh_att[t] = num / den;
    }
    __syncthreads();

    // ---- wp matvec (1024 threads, 16 rows each) ----
    float4 s4 = make_float4(0, 0, 0, 0);
#pragma unroll
    for (int i = 0; i < 16; i++) {
        int c = r * 16 + i;
        float g = sh_att[c];
        float4 a = ((const float4*)(wp + (size_t)c * C_))[u];
        s4.x = fmaf(g, a.x, s4.x); s4.y = fmaf(g, a.y, s4.y);
        s4.z = fmaf(g, a.z, s4.z); s4.w = fmaf(g, a.w, s4.w);
    }
    __syncthreads();
    red[r][u] = s4; __syncthreads();
    if (t < 256) {
        float s = 0.f;
#pragma unroll
        for (int rr = 0; rr < 16; rr++) s += ((const float*)&red[rr][t >> 2])[t & 3];
        sh_cm[t] = 1.0f / (1.0f + ex2f(-s * LOG2E));
    }
    __syncthreads();

    // ---- percentile rank (pos 25.5 -> 0.5*(s[25]+s[26])), spread ----
    {
        float cm = sh_cm[col];
        int cnt = 0;
#pragma unroll 8
        for (int j = seg * 64; j < seg * 64 + 64; j++) {
            float cj = sh_cm[j];
            cnt += (cj < cm) || (cj == cm && j < col);
        }
        ibuf[t] = cnt;
    }
    __syncthreads();
    if (t < 256) {
        int rank = ibuf[t] + ibuf[t + 256] + ibuf[t + 512] + ibuf[t + 768];
        float cm = sh_cm[t];
        if (rank == 25) sh_scal[2] = cm;
        if (rank == 26) sh_scal[3] = cm;
    }
    __syncthreads();
    if (t < 256) {
        float cm  = sh_cm[t];
        float thr = 0.5f * (sh_scal[2] + sh_scal[3]);
        float pm  = (cm > thr) ? cm : 0.f;
        float rs  = rsqrtf(bn_v[t] + EPSF) * bn_g[t];
        float a   = (1.f + cm) * rs * pm;
        float d   = (bn_b[t] - bn_m[t] * rs) * pm;
#pragma unroll
        for (int f = 0; f < 3; f++) g_wf[(b * C_ + t) * 3 + f] = a * wqkv[t * 3 + f];
        sh_d[t] = d;
    }
    __syncthreads();
    if (t < 3) {
        float cf = 0.f;
        for (int c = 0; c < C_; c++) cf = fmaf(sh_d[c], wqkv[c * 3 + t], cf);
        g_cf[b * 3 + t] = cf;
    }
}

// ---------------------------------------------------------------------------
// K4: qkv projection, warp-per-pixel. grid (74, B), 256 thr.
// ---------------------------------------------------------------------------
__global__ void k_qkv(const float* __restrict__ x) {
    int b = blockIdx.y, t = threadIdx.x, lane = t & 31, wid = t >> 5;

    const float* wf = g_wf + b * C_ * 3;
    float wq_[8], wk_[8], wv_[8];
#pragma unroll
    for (int i = 0; i < 4; i++) {
        int c0 = 4 * lane + i, c1 = 128 + 4 * lane + i;
        wq_[i]     = wf[c0 * 3 + 0]; wk_[i]     = wf[c0 * 3 + 1]; wv_[i]     = wf[c0 * 3 + 2];
        wq_[4 + i] = wf[c1 * 3 + 0]; wk_[4 + i] = wf[c1 * 3 + 1]; wv_[4 + i] = wf[c1 * 3 + 2];
    }
    float cf0 = g_cf[b * 3 + 0], cf1 = g_cf[b * 3 + 1], cf2 = g_cf[b * 3 + 2];

    const float4* x4 = (const float4*)(x + (size_t)b * N_ * C_);
    int w = blockIdx.x * 8 + wid;
    float lmax = -1e30f, lmin = 1e30f;

#pragma unroll
    for (int i = 0; i < 7; i++) {
        int p = w + 592 * i;
        if (p < N_) {
            float4 a0 = x4[(size_t)p * 64 + lane];
            float4 a1 = x4[(size_t)p * 64 + 32 + lane];
            float q, k, v;
            q = a0.x * wq_[0]; k = a0.x * wk_[0]; v = a0.x * wv_[0];
            q = fmaf(a0.y, wq_[1], q); k = fmaf(a0.y, wk_[1], k); v = fmaf(a0.y, wv_[1], v);
            q = fmaf(a0.z, wq_[2], q); k = fmaf(a0.z, wk_[2], k); v = fmaf(a0.z, wv_[2], v);
            q = fmaf(a0.w, wq_[3], q); k = fmaf(a0.w, wk_[3], k); v = fmaf(a0.w, wv_[3], v);
            q = fmaf(a1.x, wq_[4], q); k = fmaf(a1.x, wk_[4], k); v = fmaf(a1.x, wv_[4], v);
            q = fmaf(a1.y, wq_[5], q); k = fmaf(a1.y, wk_[5], k); v = fmaf(a1.y, wv_[5], v);
            q = fmaf(a1.z, wq_[6], q); k = fmaf(a1.z, wk_[6], k); v = fmaf(a1.z, wv_[6], v);
            q = fmaf(a1.w, wq_[7], q); k = fmaf(a1.w, wk_[7], k); v = fmaf(a1.w, wv_[7], v);
#pragma unroll
            for (int o = 16; o > 0; o >>= 1) {
                q += __shfl_xor_sync(0xffffffffu, q, o);
                k += __shfl_xor_sync(0xffffffffu, k, o);
                v += __shfl_xor_sync(0xffffffffu, v, o);
            }
            float kk = k + cf1;
            lmax = fmaxf(lmax, kk); lmin = fminf(lmin, kk);
            if (lane == 0) {
                g_qs[b * N_ + p] = q + cf0;
                g_ks[b * N_ + p] = kk;
                g_vs[b * N_ + p] = v + cf2;
            }
        }
    }
    if (lane == 0) {
        atomicMax(&g_kmax_u[b], encf(lmax));
        atomicMin(&g_kmin_u[b], encf(lmin));
    }
}

// ---------------------------------------------------------------------------
// K5: spatial softmax attention. grid (111, B) = 444 blocks = one perfectly
// balanced wave at 3 blocks/SM. Warps 0-4: 5 rows, warps 5-7: 4 rows (37/blk).
// ---------------------------------------------------------------------------
template <int NR>
__device__ __forceinline__ void attn_rows(const float4* skv4, int lane, int b, int i0,
                                          float kmx, float kmn, float* __restrict__ out) {
    float c1[NR], mb[NR], num[NR], den[NR], num2[NR], den2[NR];
#pragma unroll
    for (int s = 0; s < NR; s++) {
        int i = i0 + s;
        float qi = g_qs[b * N_ + ((i < N_) ? i : (N_ - 1))];
        float m  = (qi >= 0.f) ? qi * kmx : qi * kmn;
        c1[s] = qi * LOG2E; mb[s] = m * LOG2E;
        num[s] = 0.f; den[s] = 0.f; num2[s] = 0.f; den2[s] = 0.f;
    }
#pragma unroll 2
    for (int p = lane; p < N_ / 2; p += 32) {
        float4 kv = skv4[p];
#pragma unroll
        for (int s = 0; s < NR; s++) {
            float e0 = ex2f(fmaf(c1[s], kv.x, -mb[s]));
            den[s] += e0;
            num[s] = fmaf(e0, kv.y, num[s]);
            float e1 = ex2f(fmaf(c1[s], kv.z, -mb[s]));
            den2[s] += e1;
            num2[s] = fmaf(e1, kv.w, num2[s]);
        }
    }
#pragma unroll
    for (int s = 0; s < NR; s++) {
        float n = num[s] + num2[s], d = den[s] + den2[s];
#pragma unroll
        for (int o = 16; o > 0; o >>= 1) {
            n += __shfl_xor_sync(0xffffffffu, n, o);
            d += __shfl_xor_sync(0xffffffffu, d, o);
        }
        int i = i0 + s;
        if (lane == 0 && i < N_) out[b * N_ + i] = g_vs[b * N_ + i] + n / d;
    }
}

__global__ void __launch_bounds__(256) k_attn(float* __restrict__ out) {
    __shared__ float4 skv4[N_ / 2];
    int b = blockIdx.y, t = threadIdx.x, lane = t & 31, wid = t >> 5;

    const float2* kp = (const float2*)(g_ks + b * N_);
    const float2* vp = (const float2*)(g_vs + b * N_);
    for (int p = t; p < N_ / 2; p += 256) {
        float2 k2 = kp[p], v2 = vp[p];
        skv4[p] = make_float4(k2.x, v2.x, k2.y, v2.y);
    }
    __syncthreads();

    float kmx = decf(g_kmax_u[b]), kmn = decf(g_kmin_u[b]);
    int base = blockIdx.x * ARPB;

    if (wid < 5)
        attn_rows<5>(skv4, lane, b, base + wid * 5, kmx, kmn, out);
    else
        attn_rows<4>(skv4, lane, b, base + 25 + (wid - 5) * 4, kmx, kmn, out);
}

// ---------------------------------------------------------------------------
extern "C" void kernel_launch(void* const* d_in, const int* in_sizes, int n_in,
                              void* d_out, int out_size) {
    const float* x    = (const float*)d_in[0];
    const float* ca_g = (const float*)d_in[1];
    const float* ca_b = (const float*)d_in[2];
    const float* ca_m = (const float*)d_in[3];
    const float* ca_v = (const float*)d_in[4];
    const float* wq   = (const float*)d_in[5];
    const float* wk   = (const float*)d_in[6];
    const float* wv   = (const float*)d_in[7];
    const float* wp   = (const float*)d_in[8];
    const float* bn_g = (const float*)d_in[9];
    const float* bn_b = (const float*)d_in[10];
    const float* bn_m = (const float*)d_in[11];
    const float* bn_v = (const float*)d_in[12];
    const float* wqkv = (const float*)d_in[13];
    float* out = (float*)d_out;

    k_gap<<<dim3(GCH, B_), 256>>>(x);
    k_mv<<<dim3(16, B_), 256>>>(ca_g, ca_b, ca_m, ca_v, wq, wk, wv);
    k_fin<<<B_, 1024>>>(wp, bn_g, bn_b, bn_m, bn_v, wqkv);
    k_qkv<<<dim3(74, B_), 256>>>(x);
    k_attn<<<dim3(ABL, B_), 256>>>(out);
}

// round 8
// speedup vs baseline: 2.3779x; 1.0097x over previous
#include <cuda_runtime.h>

#define C_    256
#define B_    4
#define N_    4096
#define EPSF  1e-3f
#define LOG2E 1.4426950408889634f
#define GCH   128    // gap partial chunks per batch
#define ABL   111    // attention blocks per batch (111*37 >= 4096, 444 = 148*3)
#define ARPB  37     // attention rows per block

// ---- scratch (device globals, no allocations) ----
__device__ float g_partial[B_ * GCH * C_];
__device__ float g_mv[B_ * 16 * 3 * C_];    // matvec partials [b][seg][m][c]
__device__ float g_wf[B_ * C_ * 3];
__device__ float g_cf[B_ * 3];
__device__ float g_qs[B_ * N_];
__device__ float g_ks[B_ * N_];
__device__ float g_vs[B_ * N_];
__device__ unsigned g_kmax_u[B_];
__device__ unsigned g_kmin_u[B_];

__device__ __forceinline__ float ex2f(float x) {
    float r;
    asm("ex2.approx.ftz.f32 %0, %1;" : "=f"(r) : "f"(x));
    return r;
}
__device__ __forceinline__ unsigned encf(float f) {
    unsigned u = __float_as_uint(f);
    return (u & 0x80000000u) ? ~u : (u | 0x80000000u);
}
__device__ __forceinline__ float decf(unsigned u) {
    return __uint_as_float((u & 0x80000000u) ? (u ^ 0x80000000u) : ~u);
}
__device__ __forceinline__ void l2_prefetch(const void* p) {
    asm volatile("prefetch.global.L2 [%0];" :: "l"(p));
}

// ---------------------------------------------------------------------------
// K1: GAP partials with float4 coalesced loads. grid (GCH, B), 256 thr.
// Also prefetches wq/wk/wv/wp (1 MB) into L2 for the downstream kernels.
// ---------------------------------------------------------------------------
__global__ void k_gap(const float* __restrict__ x,
                      const float* __restrict__ wq, const float* __restrict__ wk,
                      const float* __restrict__ wv, const float* __restrict__ wp) {
    __shared__ float4 sh[4][64];
    int b = blockIdx.y, blk = blockIdx.x, t = threadIdx.x;
    if (blk == 0 && b == 0 && t < B_) {
        g_kmax_u[t] = 0u;
        g_kmin_u[t] = 0xffffffffu;
    }
    // L2 prefetch: 512 blocks x 4 lines x 4 matrices = full 1 MB
    if (t < 16) {
        int g = b * GCH + blk;                  // 0..511
        int line = g * 4 + (t & 3);             // 0..2047 (128B lines, 256KB each)
        const float* base = (t >> 2) == 0 ? wq : (t >> 2) == 1 ? wk : (t >> 2) == 2 ? wv : wp;
        l2_prefetch(base + line * 32);
    }
    int c4 = t & 63, rs = t >> 6;
    const float4* xp = (const float4*)(x + (size_t)b * N_ * C_);
    float4 s = make_float4(0.f, 0.f, 0.f, 0.f);
#pragma unroll
    for (int i = 0; i < 8; i++) {
        int row = blk * 32 + rs + 4 * i;
        float4 a = xp[(size_t)row * 64 + c4];
        s.x += a.x; s.y += a.y; s.z += a.z; s.w += a.w;
    }
    sh[rs][c4] = s;
    __syncthreads();
    if (t < 64) {
        float4 a = sh[0][t], bb = sh[1][t], c = sh[2][t], d = sh[3][t];
        float4 r;
        r.x = a.x + bb.x + c.x + d.x;
        r.y = a.y + bb.y + c.y + d.y;
        r.z = a.z + bb.z + c.z + d.z;
        r.w = a.w + bb.w + c.w + d.w;
        ((float4*)(g_partial + (size_t)(b * GCH + blk) * C_))[t] = r;
    }
}

// ---------------------------------------------------------------------------
// K2: gap-final + BN + q/k/v matvec PARTIALS. grid (16, B), 256 thr.
// ---------------------------------------------------------------------------
__global__ void __launch_bounds__(256) k_mv(
        const float* __restrict__ ca_g, const float* __restrict__ ca_b,
        const float* __restrict__ ca_m, const float* __restrict__ ca_v,
        const float* __restrict__ wq,   const float* __restrict__ wk,
        const float* __restrict__ wv) {
    __shared__ float4 red[4][65];
    __shared__ float sh_gn[16];
    int seg = blockIdx.x, b = blockIdx.y, t = threadIdx.x;
    int u = t & 63, r2 = t >> 6;
    float* rb = (float*)red;

    // gap final for this segment's 16 channels: thread (c_l, piece)
    {
        int c_l = t >> 4, piece = t & 15;
        float s = 0.f;
#pragma unroll
        for (int j = 0; j < 8; j++)
            s += g_partial[(size_t)(b * GCH + piece * 8 + j) * C_ + seg * 16 + c_l];
        rb[c_l * 16 + piece] = s;
    }
    __syncthreads();
    if (t < 16) {
        float ss = 0.f;
#pragma unroll
        for (int p = 0; p < 16; p++) ss += rb[t * 16 + p];
        float gap = ss * (1.f / N_);
        int c = seg * 16 + t;
        sh_gn[t] = (gap - ca_m[c]) * rsqrtf(ca_v[c] + EPSF) * ca_g[c] + ca_b[c];
    }
    __syncthreads();

    // matvec partials over 16 channel-rows; thread owns cols 4u..4u+3
    float4 q4 = make_float4(0, 0, 0, 0), k4 = q4, v4 = q4;
#pragma unroll
    for (int i = 0; i < 4; i++) {
        int cl = r2 * 4 + i;
        int c  = seg * 16 + cl;
        float gg = sh_gn[cl];
        float4 a = ((const float4*)(wq + (size_t)c * C_))[u];
        q4.x = fmaf(gg, a.x, q4.x); q4.y = fmaf(gg, a.y, q4.y);
        q4.z = fmaf(gg, a.z, q4.z); q4.w = fmaf(gg, a.w, q4.w);
        float4 bb = ((const float4*)(wk + (size_t)c * C_))[u];
        k4.x = fmaf(gg, bb.x, k4.x); k4.y = fmaf(gg, bb.y, k4.y);
        k4.z = fmaf(gg, bb.z, k4.z); k4.w = fmaf(gg, bb.w, k4.w);
        float4 cc = ((const float4*)(wv + (size_t)c * C_))[u];
        v4.x = fmaf(gg, cc.x, v4.x); v4.y = fmaf(gg, cc.y, v4.y);
        v4.z = fmaf(gg, cc.z, v4.z); v4.w = fmaf(gg, cc.w, v4.w);
    }
    float* mv = g_mv + (size_t)(b * 16 + seg) * 3 * C_;
    __syncthreads();
    red[r2][u] = q4; __syncthreads();
    if (t < 64) {
        float4 a = red[0][t], bb = red[1][t], c = red[2][t], d = red[3][t];
        ((float4*)mv)[t] = make_float4(a.x + bb.x + c.x + d.x, a.y + bb.y + c.y + d.y,
                                       a.z + bb.z + c.z + d.z, a.w + bb.w + c.w + d.w);
    }
    __syncthreads();
    red[r2][u] = k4; __syncthreads();
    if (t < 64) {
        float4 a = red[0][t], bb = red[1][t], c = red[2][t], d = red[3][t];
        ((float4*)(mv + C_))[t] = make_float4(a.x + bb.x + c.x + d.x, a.y + bb.y + c.y + d.y,
                                              a.z + bb.z + c.z + d.z, a.w + bb.w + c.w + d.w);
    }
    __syncthreads();
    red[r2][u] = v4; __syncthreads();
    if (t < 64) {
        float4 a = red[0][t], bb = red[1][t], c = red[2][t], d = red[3][t];
        ((float4*)(mv + 2 * C_))[t] = make_float4(a.x + bb.x + c.x + d.x, a.y + bb.y + c.y + d.y,
                                                  a.z + bb.z + c.z + d.z, a.w + bb.w + c.w + d.w);
    }
}

// ---------------------------------------------------------------------------
// K3: finalize channel attention. grid B, 1024 thr.
// ---------------------------------------------------------------------------
__global__ void __launch_bounds__(1024) k_fin(
        const float* __restrict__ wp,
        const float* __restrict__ bn_g, const float* __restrict__ bn_b,
        const float* __restrict__ bn_m, const float* __restrict__ bn_v,
        const float* __restrict__ wqkv) {
    __shared__ float4 red[16][65];
    __shared__ float sh_q[C_], sh_k[C_], sh_v[C_];
    __shared__ float sh_att[C_], sh_cm[C_], sh_d[C_];
    __shared__ float sh_mx[8], sh_mn[8], sh_scal[4];
    float* rbuf = (float*)red;
    int*   ibuf = (int*)red;
    int b = blockIdx.x, t = threadIdx.x;
    int lane = t & 31, wid = t >> 5;
    int col = t & 255, seg = t >> 8;
    int u = t & 63, r = t >> 6;

    // ---- reduce q/k/v partials over 16 segments, spread over 4 ----
    {
        float qf = 0.f, kf = 0.f, vf = 0.f;
#pragma unroll
        for (int s2 = 0; s2 < 4; s2++) {
            const float* mv = g_mv + (size_t)(b * 16 + seg * 4 + s2) * 3 * C_;
            qf += mv[col]; kf += mv[C_ + col]; vf += mv[2 * C_ + col];
        }
        rbuf[t] = qf; rbuf[1024 + t] = kf; rbuf[2048 + t] = vf;
    }
    __syncthreads();
    if (t < 256) {
        sh_q[t] = rbuf[t] + rbuf[t + 256] + rbuf[t + 512] + rbuf[t + 768];
        sh_k[t] = rbuf[1024 + t] + rbuf[1024 + t + 256] + rbuf[1024 + t + 512] + rbuf[1024 + t + 768];
        sh_v[t] = rbuf[2048 + t] + rbuf[2048 + t + 256] + rbuf[2048 + t + 512] + rbuf[2048 + t + 768];
    }
    __syncthreads();

    // ---- k min/max ----
    if (t < 256) {
        float kk = sh_k[t];
        float mx = kk, mn = kk;
#pragma unroll
        for (int o = 16; o > 0; o >>= 1) {
            mx = fmaxf(mx, __shfl_xor_sync(0xffffffffu, mx, o));
            mn = fminf(mn, __shfl_xor_sync(0xffffffffu, mn, o));
        }
        if (lane == 0) { sh_mx[wid] = mx; sh_mn[wid] = mn; }
    }
    __syncthreads();
    if (t == 0) {
        float mx = sh_mx[0], mn = sh_mn[0];
        for (int i = 1; i < 8; i++) { mx = fmaxf(mx, sh_mx[i]); mn = fminf(mn, sh_mn[i]); }
        sh_scal[0] = mx; sh_scal[1] = mn;
    }
    __syncthreads();

    // ---- channel softmax, spread over 4 segments ----
    {
        float q = sh_q[col];
        float m = (q >= 0.f) ? q * sh_scal[0] : q * sh_scal[1];
        float c1 = q * LOG2E, mb = m * LOG2E;
        float num = 0.f, den = 0.f;
#pragma unroll 8
        for (int j = seg * 64; j < seg * 64 + 64; j++) {
            float e = ex2f(fmaf(c1, sh_k[j], -mb));
            den += e;
            num = fmaf(e, sh_v[j], num);
        }
        rbuf[t] = num; rbuf[2048 + t] = den;
    }
    __syncthreads();
    if (t < 256) {
        float num = rbuf[t] + rbuf[t + 256] + rbuf[t + 512] + rbuf[t + 768];
        float den = rbuf[2048 + t] + rbuf[2048 + t + 256] + rbuf[2048 + t + 512] + rbuf[2048 + t + 768];
        sh_att[t] = num / den;
    }
    __syncthreads();

    // ---- wp matvec (1024 threads, 16 rows each) ----
    float4 s4 = make_float4(0, 0, 0, 0);
#pragma unroll
    for (int i = 0; i < 16; i++) {
        int c = r * 16 + i;
        float g = sh_att[c];
        float4 a = ((const float4*)(wp + (size_t)c * C_))[u];
        s4.x = fmaf(g, a.x, s4.x); s4.y = fmaf(g, a.y, s4.y);
        s4.z = fmaf(g, a.z, s4.z); s4.w = fmaf(g, a.w, s4.w);
    }
    __syncthreads();
    red[r][u] = s4; __syncthreads();
    if (t < 256) {
        float s = 0.f;
#pragma unroll
        for (int rr = 0; rr < 16; rr++) s += ((const float*)&red[rr][t >> 2])[t & 3];
        sh_cm[t] = 1.0f / (1.0f + ex2f(-s * LOG2E));
    }
    __syncthreads();

    // ---- percentile rank (pos 25.5 -> 0.5*(s[25]+s[26])), spread ----
    {
        float cm = sh_cm[col];
        int cnt = 0;
#pragma unroll 8
        for (int j = seg * 64; j < seg * 64 + 64; j++) {
            float cj = sh_cm[j];
            cnt += (cj < cm) || (cj == cm && j < col);
        }
        ibuf[t] = cnt;
    }
    __syncthreads();
    if (t < 256) {
        int rank = ibuf[t] + ibuf[t + 256] + ibuf[t + 512] + ibuf[t + 768];
        float cm = sh_cm[t];
        if (rank == 25) sh_scal[2] = cm;
        if (rank == 26) sh_scal[3] = cm;
    }
    __syncthreads();
    if (t < 256) {
        float cm  = sh_cm[t];
        float thr = 0.5f * (sh_scal[2] + sh_scal[3]);
        float pm  = (cm > thr) ? cm : 0.f;
        float rs  = rsqrtf(bn_v[t] + EPSF) * bn_g[t];
        float a   = (1.f + cm) * rs * pm;
        float d   = (bn_b[t] - bn_m[t] * rs) * pm;
#pragma unroll
        for (int f = 0; f < 3; f++) g_wf[(b * C_ + t) * 3 + f] = a * wqkv[t * 3 + f];
        sh_d[t] = d;
    }
    __syncthreads();
    if (t < 3) {
        float cf = 0.f;
        for (int c = 0; c < C_; c++) cf = fmaf(sh_d[c], wqkv[c * 3 + t], cf);
        g_cf[b * 3 + t] = cf;
    }
}

// ---------------------------------------------------------------------------
// K4: qkv projection, warp-per-pixel, software-pipelined (MLP=4).
// grid (128, B) = 512 blocks, 8 warps, exactly 4 pixels per warp.
// ---------------------------------------------------------------------------
__device__ __forceinline__ void qkv_compute(
        float4 a0, float4 a1, const float* wq_, const float* wk_, const float* wv_,
        float cf0, float cf1, float cf2, int b, int p,
        float& lmax, float& lmin, int lane) {
    float q, k, v;
    q = a0.x * wq_[0]; k = a0.x * wk_[0]; v = a0.x * wv_[0];
    q = fmaf(a0.y, wq_[1], q); k = fmaf(a0.y, wk_[1], k); v = fmaf(a0.y, wv_[1], v);
    q = fmaf(a0.z, wq_[2], q); k = fmaf(a0.z, wk_[2], k); v = fmaf(a0.z, wv_[2], v);
    q = fmaf(a0.w, wq_[3], q); k = fmaf(a0.w, wk_[3], k); v = fmaf(a0.w, wv_[3], v);
    q = fmaf(a1.x, wq_[4], q); k = fmaf(a1.x, wk_[4], k); v = fmaf(a1.x, wv_[4], v);
    q = fmaf(a1.y, wq_[5], q); k = fmaf(a1.y, wk_[5], k); v = fmaf(a1.y, wv_[5], v);
    q = fmaf(a1.z, wq_[6], q); k = fmaf(a1.z, wk_[6], k); v = fmaf(a1.z, wv_[6], v);
    q = fmaf(a1.w, wq_[7], q); k = fmaf(a1.w, wk_[7], k); v = fmaf(a1.w, wv_[7], v);
#pragma unroll
    for (int o = 16; o > 0; o >>= 1) {
        q += __shfl_xor_sync(0xffffffffu, q, o);
        k += __shfl_xor_sync(0xffffffffu, k, o);
        v += __shfl_xor_sync(0xffffffffu, v, o);
    }
    float kk = k + cf1;
    lmax = fmaxf(lmax, kk); lmin = fminf(lmin, kk);
    if (lane == 0) {
        g_qs[b * N_ + p] = q + cf0;
        g_ks[b * N_ + p] = kk;
        g_vs[b * N_ + p] = v + cf2;
    }
}

__global__ void __launch_bounds__(256, 4) k_qkv(const float* __restrict__ x) {
    __shared__ float swf[C_ * 3];
    int b = blockIdx.y, t = threadIdx.x, lane = t & 31, wid = t >> 5;

    for (int i = t; i < C_ * 3; i += 256) swf[i] = g_wf[b * C_ * 3 + i];
    __syncthreads();

    float wq_[8], wk_[8], wv_[8];
#pragma unroll
    for (int i = 0; i < 4; i++) {
        int c0 = 4 * lane + i, c1 = 128 + 4 * lane + i;
        wq_[i]     = swf[c0 * 3 + 0]; wk_[i]     = swf[c0 * 3 + 1]; wv_[i]     = swf[c0 * 3 + 2];
        wq_[4 + i] = swf[c1 * 3 + 0]; wk_[4 + i] = swf[c1 * 3 + 1]; wv_[4 + i] = swf[c1 * 3 + 2];
    }
    float cf0 = g_cf[b * 3 + 0], cf1 = g_cf[b * 3 + 1], cf2 = g_cf[b * 3 + 2];

    const float4* x4 = (const float4*)(x + (size_t)b * N_ * C_);
    int w = blockIdx.x * 8 + wid;          // 0..1023; pixels w*4 .. w*4+3
    float lmax = -1e30f, lmin = 1e30f;

    int p0 = w * 4;
    float4 c0 = x4[(size_t)p0 * 64 + lane];
    float4 c1 = x4[(size_t)p0 * 64 + 32 + lane];
#pragma unroll
    for (int i = 0; i < 4; i++) {
        float4 n0, n1;
        if (i < 3) {
            n0 = x4[(size_t)(p0 + i + 1) * 64 + lane];
            n1 = x4[(size_t)(p0 + i + 1) * 64 + 32 + lane];
        }
        qkv_compute(c0, c1, wq_, wk_, wv_, cf0, cf1, cf2, b, p0 + i, lmax, lmin, lane);
        c0 = n0; c1 = n1;
    }
    if (lane == 0) {
        atomicMax(&g_kmax_u[b], encf(lmax));
        atomicMin(&g_kmin_u[b], encf(lmin));
    }
}

// ---------------------------------------------------------------------------
// K5: spatial softmax attention. grid (111, B) = 444 blocks = one perfectly
// balanced wave at 3 blocks/SM. Warps 0-4: 5 rows, warps 5-7: 4 rows (37/blk).
// ---------------------------------------------------------------------------
template <int NR>
__device__ __forceinline__ void attn_rows(const float4* skv4, int lane, int b, int i0,
                                          float kmx, float kmn, float* __restrict__ out) {
    float c1[NR], mb[NR], num[NR], den[NR], num2[NR], den2[NR];
#pragma unroll
    for (int s = 0; s < NR; s++) {
        int i = i0 + s;
        float qi = g_qs[b * N_ + ((i < N_) ? i : (N_ - 1))];
        float m  = (qi >= 0.f) ? qi * kmx : qi * kmn;
        c1[s] = qi * LOG2E; mb[s] = m * LOG2E;
        num[s] = 0.f; den[s] = 0.f; num2[s] = 0.f; den2[s] = 0.f;
    }
#pragma unroll 2
    for (int p = lane; p < N_ / 2; p += 32) {
        float4 kv = skv4[p];
#pragma unroll
        for (int s = 0; s < NR; s++) {
            float e0 = ex2f(fmaf(c1[s], kv.x, -mb[s]));
            den[s] += e0;
            num[s] = fmaf(e0, kv.y, num[s]);
            float e1 = ex2f(fmaf(c1[s], kv.z, -mb[s]));
            den2[s] += e1;
            num2[s] = fmaf(e1, kv.w, num2[s]);
        }
    }
#pragma unroll
    for (int s = 0; s < NR; s++) {
        float n = num[s] + num2[s], d = den[s] + den2[s];
#pragma unroll
        for (int o = 16; o > 0; o >>= 1) {
            n += __shfl_xor_sync(0xffffffffu, n, o);
            d += __shfl_xor_sync(0xffffffffu, d, o);
        }
        int i = i0 + s;
        if (lane == 0 && i < N_) out[b * N_ + i] = g_vs[b * N_ + i] + n / d;
    }
}

__global__ void __launch_bounds__(256) k_attn(float* __restrict__ out) {
    __shared__ float4 skv4[N_ / 2];
    int b = blockIdx.y, t = threadIdx.x, lane = t & 31, wid = t >> 5;

    const float2* kp = (const float2*)(g_ks + b * N_);
    const float2* vp = (const float2*)(g_vs + b * N_);
    for (int p = t; p < N_ / 2; p += 256) {
        float2 k2 = kp[p], v2 = vp[p];
        skv4[p] = make_float4(k2.x, v2.x, k2.y, v2.y);
    }
    __syncthreads();

    float kmx = decf(g_kmax_u[b]), kmn = decf(g_kmin_u[b]);
    int base = blockIdx.x * ARPB;

    if (wid < 5)
        attn_rows<5>(skv4, lane, b, base + wid * 5, kmx, kmn, out);
    else
        attn_rows<4>(skv4, lane, b, base + 25 + (wid - 5) * 4, kmx, kmn, out);
}

// ---------------------------------------------------------------------------
extern "C" void kernel_launch(void* const* d_in, const int* in_sizes, int n_in,
                              void* d_out, int out_size) {
    const float* x    = (const float*)d_in[0];
    const float* ca_g = (const float*)d_in[1];
    const float* ca_b = (const float*)d_in[2];
    const float* ca_m = (const float*)d_in[3];
    const float* ca_v = (const float*)d_in[4];
    const float* wq   = (const float*)d_in[5];
    const float* wk   = (const float*)d_in[6];
    const float* wv   = (const float*)d_in[7];
    const float* wp   = (const float*)d_in[8];
    const float* bn_g = (const float*)d_in[9];
    const float* bn_b = (const float*)d_in[10];
    const float* bn_m = (const float*)d_in[11];
    const float* bn_v = (const float*)d_in[12];
    const float* wqkv = (const float*)d_in[13];
    float* out = (float*)d_out;

    k_gap<<<dim3(GCH, B_), 256>>>(x, wq, wk, wv, wp);
    k_mv<<<dim3(16, B_), 256>>>(ca_g, ca_b, ca_m, ca_v, wq, wk, wv);
    k_fin<<<B_, 1024>>>(wp, bn_g, bn_b, bn_m, bn_v, wqkv);
    k_qkv<<<dim3(128, B_), 256>>>(x);
    k_attn<<<dim3(ABL, B_), 256>>>(out);
}

// round 11
// speedup vs baseline: 2.4320x; 1.0228x over previous
#include <cuda_runtime.h>

#define C_    256
#define B_    4
#define N_    4096
#define EPSF  1e-3f
#define LOG2E 1.4426950408889634f
#define GCH   128    // gap partial chunks per batch
#define ABL   111    // attention blocks per batch (111*37 >= 4096, 444 = 148*3)
#define ARPB  37     // attention rows per block

// ---- scratch (device globals, no allocations) ----
__device__ float g_partial[B_ * GCH * C_];
__device__ float g_mv[B_ * 16 * 3 * C_];    // matvec partials [b][seg][m][c]
__device__ float g_wf[B_ * C_ * 3];
__device__ float g_cf[B_ * 3];
__device__ float g_qs[B_ * N_];
__device__ float g_ks[B_ * N_];
__device__ float g_vs[B_ * N_];
__device__ unsigned g_kmax_u[B_];
__device__ unsigned g_kmin_u[B_];

__device__ __forceinline__ float ex2f(float x) {
    float r;
    asm("ex2.approx.ftz.f32 %0, %1;" : "=f"(r) : "f"(x));
    return r;
}
__device__ __forceinline__ unsigned encf(float f) {
    unsigned u = __float_as_uint(f);
    return (u & 0x80000000u) ? ~u : (u | 0x80000000u);
}
__device__ __forceinline__ float decf(unsigned u) {
    return __uint_as_float((u & 0x80000000u) ? (u ^ 0x80000000u) : ~u);
}
__device__ __forceinline__ void l2_prefetch(const void* p) {
    asm volatile("prefetch.global.L2 [%0];" :: "l"(p));
}

// ---------------------------------------------------------------------------
// K1: GAP partials with float4 coalesced loads. grid (GCH, B), 256 thr.
// Also prefetches wq/wk/wv/wp (1 MB) into L2 for the downstream kernels.
// ---------------------------------------------------------------------------
__global__ void k_gap(const float* __restrict__ x,
                      const float* __restrict__ wq, const float* __restrict__ wk,
                      const float* __restrict__ wv, const float* __restrict__ wp) {
    __shared__ float4 sh[4][64];
    int b = blockIdx.y, blk = blockIdx.x, t = threadIdx.x;
    if (blk == 0 && b == 0 && t < B_) {
        g_kmax_u[t] = 0u;
        g_kmin_u[t] = 0xffffffffu;
    }
    // L2 prefetch: 512 blocks x 4 lines x 4 matrices = full 1 MB
    if (t < 16) {
        int g = b * GCH + blk;                  // 0..511
        int line = g * 4 + (t & 3);             // 0..2047 (128B lines, 256KB each)
        const float* base = (t >> 2) == 0 ? wq : (t >> 2) == 1 ? wk : (t >> 2) == 2 ? wv : wp;
        l2_prefetch(base + line * 32);
    }
    int c4 = t & 63, rs = t >> 6;
    const float4* xp = (const float4*)(x + (size_t)b * N_ * C_);
    float4 s = make_float4(0.f, 0.f, 0.f, 0.f);
#pragma unroll
    for (int i = 0; i < 8; i++) {
        int row = blk * 32 + rs + 4 * i;
        float4 a = xp[(size_t)row * 64 + c4];
        s.x += a.x; s.y += a.y; s.z += a.z; s.w += a.w;
    }
    sh[rs][c4] = s;
    __syncthreads();
    if (t < 64) {
        float4 a = sh[0][t], bb = sh[1][t], c = sh[2][t], d = sh[3][t];
        float4 r;
        r.x = a.x + bb.x + c.x + d.x;
        r.y = a.y + bb.y + c.y + d.y;
        r.z = a.z + bb.z + c.z + d.z;
        r.w = a.w + bb.w + c.w + d.w;
        ((float4*)(g_partial + (size_t)(b * GCH + blk) * C_))[t] = r;
    }
}

// ---------------------------------------------------------------------------
// K2: gap-final + BN + q/k/v matvec PARTIALS. grid (16, B), 256 thr.
// ---------------------------------------------------------------------------
__global__ void __launch_bounds__(256) k_mv(
        const float* __restrict__ ca_g, const float* __restrict__ ca_b,
        const float* __restrict__ ca_m, const float* __restrict__ ca_v,
        const float* __restrict__ wq,   const float* __restrict__ wk,
        const float* __restrict__ wv) {
    __shared__ float4 red[4][65];
    __shared__ float sh_gn[16];
    int seg = blockIdx.x, b = blockIdx.y, t = threadIdx.x;
    int u = t & 63, r2 = t >> 6;
    float* rb = (float*)red;

    // gap final for this segment's 16 channels: thread (c_l, piece)
    {
        int c_l = t >> 4, piece = t & 15;
        float s = 0.f;
#pragma unroll
        for (int j = 0; j < 8; j++)
            s += g_partial[(size_t)(b * GCH + piece * 8 + j) * C_ + seg * 16 + c_l];
        rb[c_l * 16 + piece] = s;
    }
    __syncthreads();
    if (t < 16) {
        float ss = 0.f;
#pragma unroll
        for (int p = 0; p < 16; p++) ss += rb[t * 16 + p];
        float gap = ss * (1.f / N_);
        int c = seg * 16 + t;
        sh_gn[t] = (gap - ca_m[c]) * rsqrtf(ca_v[c] + EPSF) * ca_g[c] + ca_b[c];
    }
    __syncthreads();

    // matvec partials over 16 channel-rows; thread owns cols 4u..4u+3
    float4 q4 = make_float4(0, 0, 0, 0), k4 = q4, v4 = q4;
#pragma unroll
    for (int i = 0; i < 4; i++) {
        int cl = r2 * 4 + i;
        int c  = seg * 16 + cl;
        float gg = sh_gn[cl];
        float4 a = ((const float4*)(wq + (size_t)c * C_))[u];
        q4.x = fmaf(gg, a.x, q4.x); q4.y = fmaf(gg, a.y, q4.y);
        q4.z = fmaf(gg, a.z, q4.z); q4.w = fmaf(gg, a.w, q4.w);
        float4 bb = ((const float4*)(wk + (size_t)c * C_))[u];
        k4.x = fmaf(gg, bb.x, k4.x); k4.y = fmaf(gg, bb.y, k4.y);
        k4.z = fmaf(gg, bb.z, k4.z); k4.w = fmaf(gg, bb.w, k4.w);
        float4 cc = ((const float4*)(wv + (size_t)c * C_))[u];
        v4.x = fmaf(gg, cc.x, v4.x); v4.y = fmaf(gg, cc.y, v4.y);
        v4.z = fmaf(gg, cc.z, v4.z); v4.w = fmaf(gg, cc.w, v4.w);
    }
    float* mv = g_mv + (size_t)(b * 16 + seg) * 3 * C_;
    __syncthreads();
    red[r2][u] = q4; __syncthreads();
    if (t < 64) {
        float4 a = red[0][t], bb = red[1][t], c = red[2][t], d = red[3][t];
        ((float4*)mv)[t] = make_float4(a.x + bb.x + c.x + d.x, a.y + bb.y + c.y + d.y,
                                       a.z + bb.z + c.z + d.z, a.w + bb.w + c.w + d.w);
    }
    __syncthreads();
    red[r2][u] = k4; __syncthreads();
    if (t < 64) {
        float4 a = red[0][t], bb = red[1][t], c = red[2][t], d = red[3][t];
        ((float4*)(mv + C_))[t] = make_float4(a.x + bb.x + c.x + d.x, a.y + bb.y + c.y + d.y,
                                              a.z + bb.z + c.z + d.z, a.w + bb.w + c.w + d.w);
    }
    __syncthreads();
    red[r2][u] = v4; __syncthreads();
    if (t < 64) {
        float4 a = red[0][t], bb = red[1][t], c = red[2][t], d = red[3][t];
        ((float4*)(mv + 2 * C_))[t] = make_float4(a.x + bb.x + c.x + d.x, a.y + bb.y + c.y + d.y,
                                                  a.z + bb.z + c.z + d.z, a.w + bb.w + c.w + d.w);
    }
}

// ---------------------------------------------------------------------------
// K3: finalize channel attention. grid B, 1024 thr.
// ---------------------------------------------------------------------------
__global__ void __launch_bounds__(1024) k_fin(
        const float* __restrict__ wp,
        const float* __restrict__ bn_g, const float* __restrict__ bn_b,
        const float* __restrict__ bn_m, const float* __restrict__ bn_v,
        const float* __restrict__ wqkv) {
    __shared__ float4 red[16][65];
    __shared__ float sh_q[C_], sh_k[C_], sh_v[C_];
    __shared__ float sh_att[C_], sh_cm[C_], sh_d[C_];
    __shared__ float sh_mx[8], sh_mn[8], sh_scal[4];
    float* rbuf = (float*)red;
    int*   ibuf = (int*)red;
    int b = blockIdx.x, t = threadIdx.x;
    int lane = t & 31, wid = t >> 5;
    int col = t & 255, seg = t >> 8;
    int u = t & 63, r = t >> 6;

    // ---- reduce q/k/v partials over 16 segments, spread over 4 ----
    {
        float qf = 0.f, kf = 0.f, vf = 0.f;
#pragma unroll
        for (int s2 = 0; s2 < 4; s2++) {
            const float* mv = g_mv + (size_t)(b * 16 + seg * 4 + s2) * 3 * C_;
            qf += mv[col]; kf += mv[C_ + col]; vf += mv[2 * C_ + col];
        }
        rbuf[t] = qf; rbuf[1024 + t] = kf; rbuf[2048 + t] = vf;
    }
    __syncthreads();
    if (t < 256) {
        sh_q[t] = rbuf[t] + rbuf[t + 256] + rbuf[t + 512] + rbuf[t + 768];
        sh_k[t] = rbuf[1024 + t] + rbuf[1024 + t + 256] + rbuf[1024 + t + 512] + rbuf[1024 + t + 768];
        sh_v[t] = rbuf[2048 + t] + rbuf[2048 + t + 256] + rbuf[2048 + t + 512] + rbuf[2048 + t + 768];
    }
    __syncthreads();

    // ---- k min/max ----
    if (t < 256) {
        float kk = sh_k[t];
        float mx = kk, mn = kk;
#pragma unroll
        for (int o = 16; o > 0; o >>= 1) {
            mx = fmaxf(mx, __shfl_xor_sync(0xffffffffu, mx, o));
            mn = fminf(mn, __shfl_xor_sync(0xffffffffu, mn, o));
        }
        if (lane == 0) { sh_mx[wid] = mx; sh_mn[wid] = mn; }
    }
    __syncthreads();
    if (t == 0) {
        float mx = sh_mx[0], mn = sh_mn[0];
        for (int i = 1; i < 8; i++) { mx = fmaxf(mx, sh_mx[i]); mn = fminf(mn, sh_mn[i]); }
        sh_scal[0] = mx; sh_scal[1] = mn;
    }
    __syncthreads();

    // ---- channel softmax, spread over 4 segments ----
    {
        float q = sh_q[col];
        float m = (q >= 0.f) ? q * sh_scal[0] : q * sh_scal[1];
        float c1 = q * LOG2E, mb = m * LOG2E;
        float num = 0.f, den = 0.f;
#pragma unroll 8
        for (int j = seg * 64; j < seg * 64 + 64; j++) {
            float e = ex2f(fmaf(c1, sh_k[j], -mb));
            den += e;
            num = fmaf(e, sh_v[j], num);
        }
        rbuf[t] = num; rbuf[2048 + t] = den;
    }
    __syncthreads();
    if (t < 256) {
        float num = rbuf[t] + rbuf[t + 256] + rbuf[t + 512] + rbuf[t + 768];
        float den = rbuf[2048 + t] + rbuf[2048 + t + 256] + rbuf[2048 + t + 512] + rbuf[2048 + t + 768];
        sh_att[t] = num / den;
    }
    __syncthreads();

    // ---- wp matvec (1024 threads, 16 rows each) ----
    float4 s4 = make_float4(0, 0, 0, 0);
#pragma unroll
    for (int i = 0; i < 16; i++) {
        int c = r * 16 + i;
        float g = sh_att[c];
        float4 a = ((const float4*)(wp + (size_t)c * C_))[u];
        s4.x = fmaf(g, a.x, s4.x); s4.y = fmaf(g, a.y, s4.y);
        s4.z = fmaf(g, a.z, s4.z); s4.w = fmaf(g, a.w, s4.w);
    }
    __syncthreads();
    red[r][u] = s4; __syncthreads();
    if (t < 256) {
        float s = 0.f;
#pragma unroll
        for (int rr = 0; rr < 16; rr++) s += ((const float*)&red[rr][t >> 2])[t & 3];
        sh_cm[t] = 1.0f / (1.0f + ex2f(-s * LOG2E));
    }
    __syncthreads();

    // ---- percentile rank (pos 25.5 -> 0.5*(s[25]+s[26])), spread ----
    {
        float cm = sh_cm[col];
        int cnt = 0;
#pragma unroll 8
        for (int j = seg * 64; j < seg * 64 + 64; j++) {
            float cj = sh_cm[j];
            cnt += (cj < cm) || (cj == cm && j < col);
        }
        ibuf[t] = cnt;
    }
    __syncthreads();
    if (t < 256) {
        int rank = ibuf[t] + ibuf[t + 256] + ibuf[t + 512] + ibuf[t + 768];
        float cm = sh_cm[t];
        if (rank == 25) sh_scal[2] = cm;
        if (rank == 26) sh_scal[3] = cm;
    }
    __syncthreads();
    if (t < 256) {
        float cm  = sh_cm[t];
        float thr = 0.5f * (sh_scal[2] + sh_scal[3]);
        float pm  = (cm > thr) ? cm : 0.f;
        float rs  = rsqrtf(bn_v[t] + EPSF) * bn_g[t];
        float a   = (1.f + cm) * rs * pm;
        float d   = (bn_b[t] - bn_m[t] * rs) * pm;
#pragma unroll
        for (int f = 0; f < 3; f++) g_wf[(b * C_ + t) * 3 + f] = a * wqkv[t * 3 + f];
        sh_d[t] = d;
    }
    __syncthreads();
    if (t < 3) {
        float cf = 0.f;
        for (int c = 0; c < C_; c++) cf = fmaf(sh_d[c], wqkv[c * 3 + t], cf);
        g_cf[b * 3 + t] = cf;
    }
}

// ---------------------------------------------------------------------------
// K4: qkv projection, 8-lane-group per pixel (4 pixels per warp concurrently).
// grid (128, B), 256 thr. Lane l8 owns channels {32j + 4*l8 .. +3}.
// Weights broadcast from smem (channel-contiguous); 3-step 8-lane reduce.
// ---------------------------------------------------------------------------
__global__ void __launch_bounds__(256, 4) k_qkv(const float* __restrict__ x) {
    __shared__ float4 swq[64], swk[64], swv[64];
    int b = blockIdx.y, t = threadIdx.x, lane = t & 31, wid = t >> 5;

    if (t < 256) {
        // thread t handles channel t: scatter g_wf[c*3+f] into contiguous arrays
        float a = g_wf[b * C_ * 3 + t * 3 + 0];
        float k = g_wf[b * C_ * 3 + t * 3 + 1];
        float v = g_wf[b * C_ * 3 + t * 3 + 2];
        ((float*)swq)[t] = a; ((float*)swk)[t] = k; ((float*)swv)[t] = v;
    }
    __syncthreads();

    float cf0 = g_cf[b * 3 + 0], cf1 = g_cf[b * 3 + 1], cf2 = g_cf[b * 3 + 2];

    int g8 = lane >> 3, l8 = lane & 7;
    int p = (blockIdx.x * 8 + wid) * 4 + g8;      // this group's pixel
    const float4* x4 = (const float4*)(x + (size_t)b * N_ * C_);

    float q = 0.f, k = 0.f, v = 0.f;
#pragma unroll
    for (int j = 0; j < 8; j++) {
        float4 a  = x4[(size_t)p * 64 + j * 8 + l8];
        float4 wq4 = swq[j * 8 + l8];
        float4 wk4 = swk[j * 8 + l8];
        float4 wv4 = swv[j * 8 + l8];
        q = fmaf(a.x, wq4.x, q); k = fmaf(a.x, wk4.x, k); v = fmaf(a.x, wv4.x, v);
        q = fmaf(a.y, wq4.y, q); k = fmaf(a.y, wk4.y, k); v = fmaf(a.y, wv4.y, v);
        q = fmaf(a.z, wq4.z, q); k = fmaf(a.z, wk4.z, k); v = fmaf(a.z, wv4.z, v);
        q = fmaf(a.w, wq4.w, q); k = fmaf(a.w, wk4.w, k); v = fmaf(a.w, wv4.w, v);
    }
    // 8-lane butterfly (stays within the group for offsets < 8)
#pragma unroll
    for (int o = 4; o > 0; o >>= 1) {
        q += __shfl_xor_sync(0xffffffffu, q, o);
        k += __shfl_xor_sync(0xffffffffu, k, o);
        v += __shfl_xor_sync(0xffffffffu, v, o);
    }
    float kk = k + cf1;
    if (l8 == 0) {
        g_qs[b * N_ + p] = q + cf0;
        g_ks[b * N_ + p] = kk;
        g_vs[b * N_ + p] = v + cf2;
    }
    // warp-wide min/max of kk (all lanes hold their group's kk)
    float lmax = kk, lmin = kk;
#pragma unroll
    for (int o = 16; o > 0; o >>= 1) {
        lmax = fmaxf(lmax, __shfl_xor_sync(0xffffffffu, lmax, o));
        lmin = fminf(lmin, __shfl_xor_sync(0xffffffffu, lmin, o));
    }
    if (lane == 0) {
        atomicMax(&g_kmax_u[b], encf(lmax));
        atomicMin(&g_kmin_u[b], encf(lmin));
    }
}

// ---------------------------------------------------------------------------
// K5: spatial softmax attention. grid (111, B) = 444 blocks = one perfectly
// balanced wave at 3 blocks/SM. Warps 0-4: 5 rows, warps 5-7: 4 rows (37/blk).
// ---------------------------------------------------------------------------
template <int NR>
__device__ __forceinline__ void attn_rows(const float4* skv4, int lane, int b, int i0,
                                          float kmx, float kmn, float* __restrict__ out) {
    float c1[NR], mb[NR], num[NR], den[NR], num2[NR], den2[NR];
#pragma unroll
    for (int s = 0; s < NR; s++) {
        int i = i0 + s;
        float qi = g_qs[b * N_ + ((i < N_) ? i : (N_ - 1))];
        float m  = (qi >= 0.f) ? qi * kmx : qi * kmn;
        c1[s] = qi * LOG2E; mb[s] = m * LOG2E;
        num[s] = 0.f; den[s] = 0.f; num2[s] = 0.f; den2[s] = 0.f;
    }
#pragma unroll 2
    for (int p = lane; p < N_ / 2; p += 32) {
        float4 kv = skv4[p];
#pragma unroll
        for (int s = 0; s < NR; s++) {
            float e0 = ex2f(fmaf(c1[s], kv.x, -mb[s]));
            den[s] += e0;
            num[s] = fmaf(e0, kv.y, num[s]);
            float e1 = ex2f(fmaf(c1[s], kv.z, -mb[s]));
            den2[s] += e1;
            num2[s] = fmaf(e1, kv.w, num2[s]);
        }
    }
#pragma unroll
    for (int s = 0; s < NR; s++) {
        float n = num[s] + num2[s], d = den[s] + den2[s];
#pragma unroll
        for (int o = 16; o > 0; o >>= 1) {
            n += __shfl_xor_sync(0xffffffffu, n, o);
            d += __shfl_xor_sync(0xffffffffu, d, o);
        }
        int i = i0 + s;
        if (lane == 0 && i < N_) out[b * N_ + i] = g_vs[b * N_ + i] + n / d;
    }
}

__global__ void __launch_bounds__(256) k_attn(float* __restrict__ out) {
    __shared__ float4 skv4[N_ / 2];
    int b = blockIdx.y, t = threadIdx.x, lane = t & 31, wid = t >> 5;

    const float2* kp = (const float2*)(g_ks + b * N_);
    const float2* vp = (const float2*)(g_vs + b * N_);
    for (int p = t; p < N_ / 2; p += 256) {
        float2 k2 = kp[p], v2 = vp[p];
        skv4[p] = make_float4(k2.x, v2.x, k2.y, v2.y);
    }
    __syncthreads();

    float kmx = decf(g_kmax_u[b]), kmn = decf(g_kmin_u[b]);
    int base = blockIdx.x * ARPB;

    if (wid < 5)
        attn_rows<5>(skv4, lane, b, base + wid * 5, kmx, kmn, out);
    else
        attn_rows<4>(skv4, lane, b, base + 25 + (wid - 5) * 4, kmx, kmn, out);
}

// ---------------------------------------------------------------------------
extern "C" void kernel_launch(void* const* d_in, const int* in_sizes, int n_in,
                              void* d_out, int out_size) {
    const float* x    = (const float*)d_in[0];
    const float* ca_g = (const float*)d_in[1];
    const float* ca_b = (const float*)d_in[2];
    const float* ca_m = (const float*)d_in[3];
    const float* ca_v = (const float*)d_in[4];
    const float* wq   = (const float*)d_in[5];
    const float* wk   = (const float*)d_in[6];
    const float* wv   = (const float*)d_in[7];
    const float* wp   = (const float*)d_in[8];
    const float* bn_g = (const float*)d_in[9];
    const float* bn_b = (const float*)d_in[10];
    const float* bn_m = (const float*)d_in[11];
    const float* bn_v = (const float*)d_in[12];
    const float* wqkv = (const float*)d_in[13];
    float* out = (float*)d_out;

    k_gap<<<dim3(GCH, B_), 256>>>(x, wq, wk, wv, wp);
    k_mv<<<dim3(16, B_), 256>>>(ca_g, ca_b, ca_m, ca_v, wq, wk, wv);
    k_fin<<<B_, 1024>>>(wp, bn_g, bn_b, bn_m, bn_v, wqkv);
    k_qkv<<<dim3(128, B_), 256>>>(x);
    k_attn<<<dim3(ABL, B_), 256>>>(out);
}